// round 10
// baseline (speedup 1.0000x reference)
#include <cuda_runtime.h>
#include <cuda_bf16.h>
#include <math.h>

#define BG   64
#define NPG  2048
#define EPG  32768
#define NTOT (BG * NPG)         // 131072
#define EDG  (BG * EPG)         // 2097152
#define K1   1639
#define NT1  (BG * K1)          // 104896 (divisible by 64)
#define K2   1312
#define NT2  (BG * K2)          // 83968
#define DIM  64
#define NCLS 6
#define CAP  64                 // fixed CSR bucket capacity (P(deg>=64) ~ 1e-20)
#define FULLMASK 0xFFFFFFFFu

typedef unsigned long long ull;

// ---------------- scratch ----------------------------------------------------
__device__ float g_xw[NTOT * DIM];       // (A@W)*rdeg  (pre-scaled rows)
__device__ float g_h[NTOT * DIM];        // conv output (relu'd)
__device__ float g_score[NTOT];
__device__ float g_rdeg[NTOT];           // rsqrt(deg incl self-loop)
__device__ int   g_cnt[NTOT];            // in-degree (excl self-loop)
__device__ int   g_elist[NTOT * CAP];    // fixed-stride CSR: src per dst-slot
__device__ int   g_perm[NT1];
__device__ float g_vals[NT1];
__device__ int   g_newid[NTOT];
__device__ float g_x1[BG * 2 * DIM];
__device__ float g_x2[BG * 2 * DIM];

// ---------------- packed f32x2 add (PTX-only; ptxas never auto-emits) --------
__device__ __forceinline__ void add2(ull& d, ull a) {
    asm("add.rn.f32x2 %0, %0, %1;" : "+l"(d) : "l"(a));
}

// ---------------- stage-1 init: cnt=0, newid=-1 ------------------------------
__global__ void init1_kernel(int* __restrict__ cnt, int* __restrict__ newid, int n) {
    int t = blockIdx.x * blockDim.x + threadIdx.x;
    int stride = gridDim.x * blockDim.x;
    for (; t < n; t += stride) { cnt[t] = 0; newid[t] = -1; }
}

// fused count + place, 4 edges/thread via int4 (stage 1: all edges valid)
__global__ void place1_kernel(const int4* __restrict__ src4, const int4* __restrict__ dst4,
                              int* __restrict__ cnt, int* __restrict__ elist, int nedge4) {
    int t = blockIdx.x * blockDim.x + threadIdx.x;
    if (t >= nedge4) return;
    int4 s = src4[t];
    int4 d = dst4[t];
    int slot;
    slot = atomicAdd(&cnt[d.x], 1); elist[d.x * CAP + slot] = s.x;
    slot = atomicAdd(&cnt[d.y], 1); elist[d.y * CAP + slot] = s.y;
    slot = atomicAdd(&cnt[d.z], 1); elist[d.z * CAP + slot] = s.z;
    slot = atomicAdd(&cnt[d.w], 1); elist[d.w * CAP + slot] = s.w;
}

// fused remap + count + place, 4 edges/thread (stage 2)
__global__ void place2_kernel(const int4* __restrict__ src4, const int4* __restrict__ dst4,
                              const int* __restrict__ newid,
                              int* __restrict__ cnt, int* __restrict__ elist, int nedge4) {
    int t = blockIdx.x * blockDim.x + threadIdx.x;
    if (t >= nedge4) return;
    int4 s = src4[t];
    int4 d = dst4[t];
    int s2, d2, slot;
    s2 = newid[s.x]; d2 = newid[d.x];
    if (s2 >= 0 && d2 >= 0) { slot = atomicAdd(&cnt[d2], 1); elist[d2 * CAP + slot] = s2; }
    s2 = newid[s.y]; d2 = newid[d.y];
    if (s2 >= 0 && d2 >= 0) { slot = atomicAdd(&cnt[d2], 1); elist[d2 * CAP + slot] = s2; }
    s2 = newid[s.z]; d2 = newid[d.z];
    if (s2 >= 0 && d2 >= 0) { slot = atomicAdd(&cnt[d2], 1); elist[d2 * CAP + slot] = s2; }
    s2 = newid[s.w]; d2 = newid[d.w];
    if (s2 >= 0 && d2 >= 0) { slot = atomicAdd(&cnt[d2], 1); elist[d2 * CAP + slot] = s2; }
}

// ---------------- GEMM: C[n x 64] = rdeg[i] * (gather(A) @ W)[i] -------------
// 64-row tile; thread = 4 rows x 4 cols. W repacked as Ws[k4][j][4] ->
// conflict-free LDS128; A reads are broadcasts. Output rows PRE-SCALED by
// rdeg[row] so the conv inner loop is a pure row sum. Also writes rdeg[].
// If perm != nullptr, row i of A is A[perm[i]] * vals[i] (fused TopK gather+gate).
__global__ __launch_bounds__(256, 4) void matmul64_kernel(
    const float* __restrict__ A, const float* __restrict__ W,
    const int* __restrict__ perm, const float* __restrict__ vals,
    float* __restrict__ C, int nrows,
    const int* __restrict__ cnt, float* __restrict__ rdeg) {
    __shared__ float Ws[16][64][4];   // [k4][col][k-in-group]
    __shared__ float As[64][64];
    int tid = threadIdx.x;
    // rdeg array pass (cnt is final here: GEMM launches after place)
    int gi = blockIdx.x * 256 + tid;
    if (gi < nrows) rdeg[gi] = rsqrtf((float)(cnt[gi] + 1));
    // repack W: W[k][j] row-major -> Ws[k>>2][j][k&3]
    for (int i = tid; i < 4096; i += 256) {
        int k = i >> 6, j = i & 63;
        Ws[k >> 2][j][k & 3] = W[i];
    }
    int row0 = blockIdx.x * 64;
    {
        float4* s4 = (float4*)&As[0][0];
        for (int i = tid; i < 1024; i += 256) {
            int grow = row0 + (i >> 4);       // grow < nrows (nrows % 64 == 0)
            int arow = perm ? perm[grow] : grow;
            float sc = perm ? vals[grow] : 1.0f;
            float4 v = ((const float4*)(A + (size_t)arow * 64))[i & 15];
            v.x *= sc; v.y *= sc; v.z *= sc; v.w *= sc;
            s4[i] = v;
        }
    }
    __syncthreads();
    int tx = tid & 15;    // col base
    int ty = tid >> 4;    // rows ty*4 .. ty*4+3
    float acc[4][4] = {};
#pragma unroll
    for (int k4 = 0; k4 < 16; k4++) {
        float4 w[4];
#pragma unroll
        for (int c = 0; c < 4; c++)
            w[c] = *(const float4*)&Ws[k4][tx + 16 * c][0];
#pragma unroll
        for (int r = 0; r < 4; r++) {
            float4 a = *(const float4*)&As[ty * 4 + r][k4 * 4];
#pragma unroll
            for (int c = 0; c < 4; c++)
                acc[r][c] += a.x * w[c].x + a.y * w[c].y + a.z * w[c].z + a.w * w[c].w;
        }
    }
#pragma unroll
    for (int r = 0; r < 4; r++) {
        int row = row0 + ty * 4 + r;
        float rr = rsqrtf((float)(cnt[row] + 1));
#pragma unroll
        for (int c = 0; c < 4; c++)
            C[(size_t)row * 64 + tx + 16 * c] = acc[r][c] * rr;
    }
}

// ---------------- fused CSR-gather conv + epilogue + score -------------------
// One warp per dst node; half-warps process alternate edge QUADS. Per quad:
// one int4 elist load + 4 independent ulonglong2 row loads accumulated with
// packed f32x2 adds (2 FADD2/edge instead of 4 FADD). No sync primitives in
// the loop -> tail divergence between halves is safe.
__global__ __launch_bounds__(256) void conv_kernel(
    const int* __restrict__ cnt, const int* __restrict__ elist,
    const float* __restrict__ rdeg, const float* __restrict__ xw,
    const float* __restrict__ bias, const float* __restrict__ p,
    float* __restrict__ h, float* __restrict__ score, int n) {
    int warp = (blockIdx.x * blockDim.x + threadIdx.x) >> 5;
    int lane = threadIdx.x & 31;
    if (warp >= n) return;
    int li   = lane & 15;
    int half = lane >> 4;
    const ulonglong2* xwp = (const ulonglong2*)xw;   // 16B per lane slice
    float rd = rdeg[warp];
    int m = cnt[warp];
    const int* el = elist + (size_t)warp * CAP;
    ull accA0 = 0, accA1 = 0;   // edges x/z of each quad
    ull accB0 = 0, accB1 = 0;   // edges y/w of each quad
    // zero-init packed pairs: bits 0 == f32x2 (0,0)  ✓
    for (int e = half * 4; e < m; e += 8) {
        int4 sp = *(const int4*)(el + e);   // 16B-aligned (e % 4 == 0)
        {
            ulonglong2 v = xwp[(size_t)sp.x * 8 + (li >> 1) * 2 + (li & 1)];
            // NOTE: index arithmetic simplified below; see addressing comment
        }
        // row slice for lane li: bytes [li*16, li*16+16) of the 256B row
        {
            ulonglong2 v = *(const ulonglong2*)((const char*)xw + ((size_t)sp.x << 8) + (li << 4));
            add2(accA0, v.x); add2(accA1, v.y);
        }
        if (e + 1 < m) {
            ulonglong2 v = *(const ulonglong2*)((const char*)xw + ((size_t)sp.y << 8) + (li << 4));
            add2(accB0, v.x); add2(accB1, v.y);
        }
        if (e + 2 < m) {
            ulonglong2 v = *(const ulonglong2*)((const char*)xw + ((size_t)sp.z << 8) + (li << 4));
            add2(accA0, v.x); add2(accA1, v.y);
        }
        if (e + 3 < m) {
            ulonglong2 v = *(const ulonglong2*)((const char*)xw + ((size_t)sp.w << 8) + (li << 4));
            add2(accB0, v.x); add2(accB1, v.y);
        }
    }
    add2(accA0, accB0);
    add2(accA1, accB1);
    float2 f01 = *(float2*)&accA0;
    float2 f23 = *(float2*)&accA1;
    float4 acc = make_float4(f01.x, f01.y, f23.x, f23.y);
    // combine halves (both halves end up with full sums)
    acc.x += __shfl_xor_sync(FULLMASK, acc.x, 16);
    acc.y += __shfl_xor_sync(FULLMASK, acc.y, 16);
    acc.z += __shfl_xor_sync(FULLMASK, acc.z, 16);
    acc.w += __shfl_xor_sync(FULLMASK, acc.w, 16);
    // epilogue: h = relu(rd*(sum + xw'[dst]) + b)
    float4 vs = ((const float4*)xw)[(size_t)warp * 16 + li];
    float4 b4 = ((const float4*)bias)[li];
    acc.x = fmaxf((acc.x + vs.x) * rd + b4.x, 0.f);
    acc.y = fmaxf((acc.y + vs.y) * rd + b4.y, 0.f);
    acc.z = fmaxf((acc.z + vs.z) * rd + b4.z, 0.f);
    acc.w = fmaxf((acc.w + vs.w) * rd + b4.w, 0.f);
    if (half == 0) ((float4*)h)[(size_t)warp * 16 + li] = acc;
    // pooling score: tanh(h.p/||p||). Both halves duplicate -> warp sums are 2x;
    // the 1/sqrt(2) factor corrects dot/sqrt(pp).
    float4 p4 = ((const float4*)p)[li];
    float dot = acc.x * p4.x + acc.y * p4.y + acc.z * p4.z + acc.w * p4.w;
    float pp  = p4.x * p4.x + p4.y * p4.y + p4.z * p4.z + p4.w * p4.w;
#pragma unroll
    for (int o = 16; o; o >>= 1) {
        dot += __shfl_down_sync(FULLMASK, dot, o);
        pp  += __shfl_down_sync(FULLMASK, pp, o);
    }
    if (lane == 0) score[warp] = tanhf(dot * rsqrtf(pp) * 0.7071067811865476f);
}

// ---------------- per-graph top-k via bitonic sort (1024 threads) ------------
// Also zeroes cnt[b*k + r] for the kept nodes (= stage-2 cnt init).
__global__ __launch_bounds__(1024) void topk_kernel(
    const float* __restrict__ score, int n_per, int k,
    int* __restrict__ perm, float* __restrict__ vals, int* __restrict__ newid,
    int* __restrict__ cnt_zero) {
    __shared__ unsigned long long keys[2048];
    int b = blockIdx.x;
    int tid = threadIdx.x;
    const float* sc = score + (size_t)b * n_per;
#pragma unroll
    for (int i = tid; i < 2048; i += 1024) {
        unsigned long long key;
        if (i < n_per) {
            unsigned u = __float_as_uint(sc[i]);
            u = (u & 0x80000000u) ? ~u : (u | 0x80000000u);
            key = ((unsigned long long)(~u) << 32) | (unsigned)i;
        } else {
            key = 0xFFFFFFFFFFFFFFFFull;
        }
        keys[i] = key;
    }
    __syncthreads();
    for (int kk = 2; kk <= 2048; kk <<= 1) {
        for (int jj = kk >> 1; jj > 0; jj >>= 1) {
#pragma unroll
            for (int i = tid; i < 2048; i += 1024) {
                int ixj = i ^ jj;
                if (ixj > i) {
                    unsigned long long a = keys[i], c = keys[ixj];
                    bool swap = ((i & kk) == 0) ? (a > c) : (a < c);
                    if (swap) { keys[i] = c; keys[ixj] = a; }
                }
            }
            __syncthreads();
        }
    }
    for (int r = tid; r < k; r += 1024) {
        int idx = (int)(keys[r] & 0xFFFFFFFFull);
        int g_old = b * n_per + idx;
        perm[b * k + r] = g_old;
        vals[b * k + r] = sc[idx];
        if (newid) newid[g_old] = b * k + r;
        if (cnt_zero) cnt_zero[b * k + r] = 0;
    }
}

// ---------------- per-graph [max | mean] over gathered+gated rows ------------
__global__ __launch_bounds__(1024) void maxmean_kernel(
    const float* __restrict__ h, const int* __restrict__ perm,
    const float* __restrict__ vals, int k, float* __restrict__ out) {
    __shared__ float smx[1024], ssm[1024];
    int b = blockIdx.x;
    int tid = threadIdx.x;
    int j = tid & 63;
    int rg = tid >> 6;          // 0..15
    float mx = -INFINITY, sum = 0.f;
    for (int r = rg; r < k; r += 16) {
        int idx = perm[b * k + r];
        float v = h[(size_t)idx * 64 + j] * vals[b * k + r];
        mx = fmaxf(mx, v);
        sum += v;
    }
    smx[tid] = mx;
    ssm[tid] = sum;
    __syncthreads();
    for (int s = 8; s >= 1; s >>= 1) {
        if (rg < s) {
            smx[rg * 64 + j] = fmaxf(smx[rg * 64 + j], smx[(rg + s) * 64 + j]);
            ssm[rg * 64 + j] += ssm[(rg + s) * 64 + j];
        }
        __syncthreads();
    }
    if (rg == 0) {
        out[b * 128 + j]      = smx[j];
        out[b * 128 + 64 + j] = ssm[j] / (float)k;
    }
}

// ---------------- MLP head ---------------------------------------------------
__global__ __launch_bounds__(64) void head_kernel(
    const float* __restrict__ x1, const float* __restrict__ x2,
    const float* __restrict__ l1w, const float* __restrict__ l1b,
    const float* __restrict__ l2w, const float* __restrict__ l2b,
    float* __restrict__ out) {
    int b = blockIdx.x;
    int j = threadIdx.x;
    __shared__ float hv[128];
    __shared__ float h1[64];
    hv[j]      = x1[b * 128 + j]      + x2[b * 128 + j];
    hv[j + 64] = x1[b * 128 + 64 + j] + x2[b * 128 + 64 + j];
    __syncthreads();
    float acc = l1b[j];
#pragma unroll 8
    for (int k = 0; k < 128; k++) acc += hv[k] * l1w[k * 64 + j];
    h1[j] = fmaxf(acc, 0.f);
    __syncthreads();
    if (j < NCLS) {
        float o = l2b[j];
#pragma unroll 8
        for (int kk = 0; kk < 64; kk++) o += h1[kk] * l2w[kk * NCLS + j];
        out[b * NCLS + j] = o;
    }
}

// ---------------- host orchestration ----------------------------------------
extern "C" void kernel_launch(void* const* d_in, const int* in_sizes, int n_in,
                              void* d_out, int out_size) {
    const float* x   = (const float*)d_in[0];
    const int* ei    = (const int*)d_in[1];
    const float* W1  = (const float*)d_in[3];
    const float* b1  = (const float*)d_in[4];
    const float* p1  = (const float*)d_in[5];
    const float* W2  = (const float*)d_in[6];
    const float* b2  = (const float*)d_in[7];
    const float* p2  = (const float*)d_in[8];
    const float* l1w = (const float*)d_in[9];
    const float* l1b = (const float*)d_in[10];
    const float* l2w = (const float*)d_in[11];
    const float* l2b = (const float*)d_in[12];
    float* out = (float*)d_out;

    const int4* src4 = (const int4*)ei;
    const int4* dst4 = (const int4*)(ei + EDG);

    float *xw, *h, *score, *rdeg, *vals, *x1, *x2;
    int *cnt, *elist, *perm, *newid;
    cudaGetSymbolAddress((void**)&xw,     g_xw);
    cudaGetSymbolAddress((void**)&h,      g_h);
    cudaGetSymbolAddress((void**)&score,  g_score);
    cudaGetSymbolAddress((void**)&rdeg,   g_rdeg);
    cudaGetSymbolAddress((void**)&cnt,    g_cnt);
    cudaGetSymbolAddress((void**)&elist,  g_elist);
    cudaGetSymbolAddress((void**)&perm,   g_perm);
    cudaGetSymbolAddress((void**)&newid,  g_newid);
    cudaGetSymbolAddress((void**)&vals,   g_vals);
    cudaGetSymbolAddress((void**)&x1,     g_x1);
    cudaGetSymbolAddress((void**)&x2,     g_x2);

    const int TB = 256;
    const int E4 = EDG / 4;
    const int EB4 = (E4 + TB - 1) / TB;

    // ===================== Stage 1 =====================
    init1_kernel<<<256, TB>>>(cnt, newid, NTOT);
    place1_kernel<<<EB4, TB>>>(src4, dst4, cnt, elist, E4);

    matmul64_kernel<<<NTOT / 64, TB>>>(x, W1, nullptr, nullptr, xw, NTOT, cnt, rdeg);
    conv_kernel<<<(NTOT * 32 + TB - 1) / TB, TB>>>(cnt, elist, rdeg, xw, b1, p1, h, score, NTOT);

    topk_kernel<<<BG, 1024>>>(score, NPG, K1, perm, vals, newid, cnt);  // zeroes cnt for stage 2
    maxmean_kernel<<<BG, 1024>>>(h, perm, vals, K1, x1);

    // ===================== Stage 2 =====================
    place2_kernel<<<EB4, TB>>>(src4, dst4, newid, cnt, elist, E4);

    matmul64_kernel<<<NT1 / 64, TB>>>(h, W2, perm, vals, xw, NT1, cnt, rdeg);
    conv_kernel<<<(NT1 * 32 + TB - 1) / TB, TB>>>(cnt, elist, rdeg, xw, b2, p2, h, score, NT1);

    topk_kernel<<<BG, 1024>>>(score, K1, K2, perm, vals, (int*)nullptr, (int*)nullptr);
    maxmean_kernel<<<BG, 1024>>>(h, perm, vals, K2, x2);

    // ===================== Head =====================
    head_kernel<<<BG, 64>>>(x1, x2, l1w, l1b, l2w, l2b, out);
}

// round 11
// speedup vs baseline: 1.1156x; 1.1156x over previous
#include <cuda_runtime.h>
#include <cuda_fp16.h>
#include <math.h>

#define BG   64
#define NPG  2048
#define EPG  32768
#define NTOT (BG * NPG)         // 131072
#define EDG  (BG * EPG)         // 2097152
#define K1   1639
#define NT1  (BG * K1)          // 104896 (divisible by 64)
#define K2   1312
#define NT2  (BG * K2)          // 83968
#define DIM  64
#define NCLS 6
#define CAP  64                 // fixed CSR bucket capacity (P(deg>=64) ~ 1e-20)
#define FULLMASK 0xFFFFFFFFu

typedef unsigned long long ull;

// ---------------- scratch ----------------------------------------------------
__device__ __half g_xw[NTOT * DIM];      // (A@W)*rdeg rows, fp16 (halves conv L2 bytes)
__device__ float  g_h[NTOT * DIM];       // conv output (relu'd), fp32
__device__ float  g_score[NTOT];
__device__ float  g_rdeg[NTOT];          // rsqrt(deg incl self-loop)
__device__ int    g_cnt[NTOT];           // in-degree (excl self-loop)
__device__ int    g_elist[NTOT * CAP];   // fixed-stride CSR: src per dst-slot
__device__ int    g_perm[NT1];
__device__ float  g_vals[NT1];
__device__ int    g_newid[NTOT];
__device__ float  g_x1[BG * 2 * DIM];
__device__ float  g_x2[BG * 2 * DIM];

// ---------------- packed f32x2 add (PTX-only; ptxas never auto-emits) --------
__device__ __forceinline__ void add2(ull& d, ull a) {
    asm("add.rn.f32x2 %0, %0, %1;" : "+l"(d) : "l"(a));
}

// ---------------- stage-1 init: cnt=0, newid=-1 ------------------------------
__global__ void init1_kernel(int* __restrict__ cnt, int* __restrict__ newid, int n) {
    int t = blockIdx.x * blockDim.x + threadIdx.x;
    int stride = gridDim.x * blockDim.x;
    for (; t < n; t += stride) { cnt[t] = 0; newid[t] = -1; }
}

// fused count + place, 4 edges/thread via int4 (stage 1: all edges valid)
__global__ void place1_kernel(const int4* __restrict__ src4, const int4* __restrict__ dst4,
                              int* __restrict__ cnt, int* __restrict__ elist, int nedge4) {
    int t = blockIdx.x * blockDim.x + threadIdx.x;
    if (t >= nedge4) return;
    int4 s = src4[t];
    int4 d = dst4[t];
    int slot;
    slot = atomicAdd(&cnt[d.x], 1); elist[d.x * CAP + slot] = s.x;
    slot = atomicAdd(&cnt[d.y], 1); elist[d.y * CAP + slot] = s.y;
    slot = atomicAdd(&cnt[d.z], 1); elist[d.z * CAP + slot] = s.z;
    slot = atomicAdd(&cnt[d.w], 1); elist[d.w * CAP + slot] = s.w;
}

// fused remap + count + place, 4 edges/thread (stage 2)
__global__ void place2_kernel(const int4* __restrict__ src4, const int4* __restrict__ dst4,
                              const int* __restrict__ newid,
                              int* __restrict__ cnt, int* __restrict__ elist, int nedge4) {
    int t = blockIdx.x * blockDim.x + threadIdx.x;
    if (t >= nedge4) return;
    int4 s = src4[t];
    int4 d = dst4[t];
    int s2, d2, slot;
    s2 = newid[s.x]; d2 = newid[d.x];
    if (s2 >= 0 && d2 >= 0) { slot = atomicAdd(&cnt[d2], 1); elist[d2 * CAP + slot] = s2; }
    s2 = newid[s.y]; d2 = newid[d.y];
    if (s2 >= 0 && d2 >= 0) { slot = atomicAdd(&cnt[d2], 1); elist[d2 * CAP + slot] = s2; }
    s2 = newid[s.z]; d2 = newid[d.z];
    if (s2 >= 0 && d2 >= 0) { slot = atomicAdd(&cnt[d2], 1); elist[d2 * CAP + slot] = s2; }
    s2 = newid[s.w]; d2 = newid[d.w];
    if (s2 >= 0 && d2 >= 0) { slot = atomicAdd(&cnt[d2], 1); elist[d2 * CAP + slot] = s2; }
}

// ---------------- GEMM: xw16[i] = fp16( rdeg[i] * (gather(A) @ W)[i] ) -------
// 64-row tile; thread = 4 rows x 4 cols. W repacked as Ws[k4][j][4] ->
// conflict-free LDS128; A reads are broadcasts. Output rows PRE-SCALED by
// rdeg[row] and stored as fp16 (conv reads half the bytes). Also writes rdeg[].
// If perm != nullptr, row i of A is A[perm[i]] * vals[i] (fused TopK gather+gate).
__global__ __launch_bounds__(256, 4) void matmul64_kernel(
    const float* __restrict__ A, const float* __restrict__ W,
    const int* __restrict__ perm, const float* __restrict__ vals,
    __half* __restrict__ C, int nrows,
    const int* __restrict__ cnt, float* __restrict__ rdeg) {
    __shared__ float Ws[16][64][4];   // [k4][col][k-in-group]
    __shared__ float As[64][64];
    int tid = threadIdx.x;
    // rdeg array pass (cnt is final here: GEMM launches after place)
    int gi = blockIdx.x * 256 + tid;
    if (gi < nrows) rdeg[gi] = rsqrtf((float)(cnt[gi] + 1));
    // repack W: W[k][j] row-major -> Ws[k>>2][j][k&3]
    for (int i = tid; i < 4096; i += 256) {
        int k = i >> 6, j = i & 63;
        Ws[k >> 2][j][k & 3] = W[i];
    }
    int row0 = blockIdx.x * 64;
    {
        float4* s4 = (float4*)&As[0][0];
        for (int i = tid; i < 1024; i += 256) {
            int grow = row0 + (i >> 4);       // grow < nrows (nrows % 64 == 0)
            int arow = perm ? perm[grow] : grow;
            float sc = perm ? vals[grow] : 1.0f;
            float4 v = ((const float4*)(A + (size_t)arow * 64))[i & 15];
            v.x *= sc; v.y *= sc; v.z *= sc; v.w *= sc;
            s4[i] = v;
        }
    }
    __syncthreads();
    int tx = tid & 15;    // col base
    int ty = tid >> 4;    // rows ty*4 .. ty*4+3
    float acc[4][4] = {};
#pragma unroll
    for (int k4 = 0; k4 < 16; k4++) {
        float4 w[4];
#pragma unroll
        for (int c = 0; c < 4; c++)
            w[c] = *(const float4*)&Ws[k4][tx + 16 * c][0];
#pragma unroll
        for (int r = 0; r < 4; r++) {
            float4 a = *(const float4*)&As[ty * 4 + r][k4 * 4];
#pragma unroll
            for (int c = 0; c < 4; c++)
                acc[r][c] += a.x * w[c].x + a.y * w[c].y + a.z * w[c].z + a.w * w[c].w;
        }
    }
#pragma unroll
    for (int r = 0; r < 4; r++) {
        int row = row0 + ty * 4 + r;
        float rr = rsqrtf((float)(cnt[row] + 1));
#pragma unroll
        for (int c = 0; c < 4; c++)
            C[(size_t)row * 64 + tx + 16 * c] = __float2half_rn(acc[r][c] * rr);
    }
}

// ---------------- fused CSR-gather conv + epilogue + score -------------------
// One warp per dst node; half-warps process alternate edges. xw rows are fp16
// pre-scaled by rdeg[src]: per edge one LDG.64 per lane (128B/row), converted
// to fp32 and accumulated with packed f32x2 adds. h written fp32.
__global__ __launch_bounds__(256) void conv_kernel(
    const int* __restrict__ cnt, const int* __restrict__ elist,
    const float* __restrict__ rdeg, const __half* __restrict__ xwh,
    const float* __restrict__ bias, const float* __restrict__ p,
    float* __restrict__ h, float* __restrict__ score, int n) {
    int warp = (blockIdx.x * blockDim.x + threadIdx.x) >> 5;
    int lane = threadIdx.x & 31;
    if (warp >= n) return;
    int li   = lane & 15;      // lane covers columns [li*4, li*4+4)
    int half = lane >> 4;
    float rd = rdeg[warp];
    int m = cnt[warp];
    const int* el = elist + (size_t)warp * CAP;
    ull a01 = 0, a23 = 0;      // packed f32x2 accumulators (bits 0 == (0.f,0.f))
    for (int e = half; e < m; e += 2) {
        int s = el[e];
        uint2 hv = *(const uint2*)((const char*)xwh + ((size_t)s << 7) + (li << 3));
        float2 f0 = __half22float2(*(const half2*)&hv.x);
        float2 f1 = __half22float2(*(const half2*)&hv.y);
        add2(a01, *(const ull*)&f0);
        add2(a23, *(const ull*)&f1);
    }
    float2 f01 = *(float2*)&a01;
    float2 f23 = *(float2*)&a23;
    float4 acc = make_float4(f01.x, f01.y, f23.x, f23.y);
    // combine halves (both halves end up with full sums)
    acc.x += __shfl_xor_sync(FULLMASK, acc.x, 16);
    acc.y += __shfl_xor_sync(FULLMASK, acc.y, 16);
    acc.z += __shfl_xor_sync(FULLMASK, acc.z, 16);
    acc.w += __shfl_xor_sync(FULLMASK, acc.w, 16);
    // self-loop term + bias + relu: h = relu(rd*(sum + xw'[dst]) + b)
    uint2 sv = *(const uint2*)((const char*)xwh + ((size_t)warp << 7) + (li << 3));
    float2 s0 = __half22float2(*(const half2*)&sv.x);
    float2 s1 = __half22float2(*(const half2*)&sv.y);
    float4 b4 = ((const float4*)bias)[li];
    acc.x = fmaxf((acc.x + s0.x) * rd + b4.x, 0.f);
    acc.y = fmaxf((acc.y + s0.y) * rd + b4.y, 0.f);
    acc.z = fmaxf((acc.z + s1.x) * rd + b4.z, 0.f);
    acc.w = fmaxf((acc.w + s1.y) * rd + b4.w, 0.f);
    if (half == 0) ((float4*)h)[(size_t)warp * 16 + li] = acc;
    // pooling score: tanh(h.p/||p||). Both halves duplicate -> warp sums are 2x;
    // the 1/sqrt(2) factor corrects dot/sqrt(pp).
    float4 p4 = ((const float4*)p)[li];
    float dot = acc.x * p4.x + acc.y * p4.y + acc.z * p4.z + acc.w * p4.w;
    float pp  = p4.x * p4.x + p4.y * p4.y + p4.z * p4.z + p4.w * p4.w;
#pragma unroll
    for (int o = 16; o; o >>= 1) {
        dot += __shfl_down_sync(FULLMASK, dot, o);
        pp  += __shfl_down_sync(FULLMASK, pp, o);
    }
    if (lane == 0) score[warp] = tanhf(dot * rsqrtf(pp) * 0.7071067811865476f);
}

// ---------------- per-graph top-k (bitonic) + FUSED max/mean readout ---------
// Sorts 2048 keys, emits perm/vals/newid/cnt-zero (optional), then computes
// the [max | mean] readout of the gathered+gated rows directly from the sorted
// keys in smem — replaces the separate maxmean kernel.
__global__ __launch_bounds__(1024) void topk_kernel(
    const float* __restrict__ score, const float* __restrict__ h,
    int n_per, int k,
    int* __restrict__ perm, float* __restrict__ vals, int* __restrict__ newid,
    int* __restrict__ cnt_zero, float* __restrict__ out) {
    __shared__ unsigned long long keys[2048];
    __shared__ float smx[1024], ssm[1024];
    int b = blockIdx.x;
    int tid = threadIdx.x;
    const float* sc = score + (size_t)b * n_per;
#pragma unroll
    for (int i = tid; i < 2048; i += 1024) {
        unsigned long long key;
        if (i < n_per) {
            unsigned u = __float_as_uint(sc[i]);
            u = (u & 0x80000000u) ? ~u : (u | 0x80000000u);
            key = ((unsigned long long)(~u) << 32) | (unsigned)i;
        } else {
            key = 0xFFFFFFFFFFFFFFFFull;
        }
        keys[i] = key;
    }
    __syncthreads();
    for (int kk = 2; kk <= 2048; kk <<= 1) {
        for (int jj = kk >> 1; jj > 0; jj >>= 1) {
#pragma unroll
            for (int i = tid; i < 2048; i += 1024) {
                int ixj = i ^ jj;
                if (ixj > i) {
                    unsigned long long a = keys[i], c = keys[ixj];
                    bool swap = ((i & kk) == 0) ? (a > c) : (a < c);
                    if (swap) { keys[i] = c; keys[ixj] = a; }
                }
            }
            __syncthreads();
        }
    }
    // emit pooling metadata (stage-1 only needs newid/cnt_zero; stage-2 skips)
    for (int r = tid; r < k; r += 1024) {
        int idx = (int)(keys[r] & 0xFFFFFFFFull);
        int g_old = b * n_per + idx;
        if (perm)     perm[b * k + r] = g_old;
        if (vals)     vals[b * k + r] = sc[idx];
        if (newid)    newid[g_old]    = b * k + r;
        if (cnt_zero) cnt_zero[b * k + r] = 0;
    }
    // fused readout: x = [max_r (h[sel_r]*val_r) | mean_r (h[sel_r]*val_r)]
    int j  = tid & 63;
    int rg = tid >> 6;          // 0..15
    float mx = -INFINITY, sum = 0.f;
    for (int r = rg; r < k; r += 16) {
        int idx = (int)(keys[r] & 0xFFFFFFFFull);
        float val = sc[idx];
        float v = h[((size_t)b * n_per + idx) * 64 + j] * val;
        mx = fmaxf(mx, v);
        sum += v;
    }
    smx[tid] = mx;
    ssm[tid] = sum;
    __syncthreads();
    for (int s = 8; s >= 1; s >>= 1) {
        if (rg < s) {
            smx[rg * 64 + j] = fmaxf(smx[rg * 64 + j], smx[(rg + s) * 64 + j]);
            ssm[rg * 64 + j] += ssm[(rg + s) * 64 + j];
        }
        __syncthreads();
    }
    if (rg == 0) {
        out[b * 128 + j]      = smx[j];
        out[b * 128 + 64 + j] = ssm[j] / (float)k;
    }
}

// ---------------- MLP head ---------------------------------------------------
__global__ __launch_bounds__(64) void head_kernel(
    const float* __restrict__ x1, const float* __restrict__ x2,
    const float* __restrict__ l1w, const float* __restrict__ l1b,
    const float* __restrict__ l2w, const float* __restrict__ l2b,
    float* __restrict__ out) {
    int b = blockIdx.x;
    int j = threadIdx.x;
    __shared__ float hv[128];
    __shared__ float h1[64];
    hv[j]      = x1[b * 128 + j]      + x2[b * 128 + j];
    hv[j + 64] = x1[b * 128 + 64 + j] + x2[b * 128 + 64 + j];
    __syncthreads();
    float acc = l1b[j];
#pragma unroll 8
    for (int k = 0; k < 128; k++) acc += hv[k] * l1w[k * 64 + j];
    h1[j] = fmaxf(acc, 0.f);
    __syncthreads();
    if (j < NCLS) {
        float o = l2b[j];
#pragma unroll 8
        for (int kk = 0; kk < 64; kk++) o += h1[kk] * l2w[kk * NCLS + j];
        out[b * NCLS + j] = o;
    }
}

// ---------------- host orchestration ----------------------------------------
extern "C" void kernel_launch(void* const* d_in, const int* in_sizes, int n_in,
                              void* d_out, int out_size) {
    const float* x   = (const float*)d_in[0];
    const int* ei    = (const int*)d_in[1];
    const float* W1  = (const float*)d_in[3];
    const float* b1  = (const float*)d_in[4];
    const float* p1  = (const float*)d_in[5];
    const float* W2  = (const float*)d_in[6];
    const float* b2  = (const float*)d_in[7];
    const float* p2  = (const float*)d_in[8];
    const float* l1w = (const float*)d_in[9];
    const float* l1b = (const float*)d_in[10];
    const float* l2w = (const float*)d_in[11];
    const float* l2b = (const float*)d_in[12];
    float* out = (float*)d_out;

    const int4* src4 = (const int4*)ei;
    const int4* dst4 = (const int4*)(ei + EDG);

    float *h, *score, *rdeg, *vals, *x1, *x2;
    __half* xwh;
    int *cnt, *elist, *perm, *newid;
    cudaGetSymbolAddress((void**)&xwh,    g_xw);
    cudaGetSymbolAddress((void**)&h,      g_h);
    cudaGetSymbolAddress((void**)&score,  g_score);
    cudaGetSymbolAddress((void**)&rdeg,   g_rdeg);
    cudaGetSymbolAddress((void**)&cnt,    g_cnt);
    cudaGetSymbolAddress((void**)&elist,  g_elist);
    cudaGetSymbolAddress((void**)&perm,   g_perm);
    cudaGetSymbolAddress((void**)&newid,  g_newid);
    cudaGetSymbolAddress((void**)&vals,   g_vals);
    cudaGetSymbolAddress((void**)&x1,     g_x1);
    cudaGetSymbolAddress((void**)&x2,     g_x2);

    const int TB = 256;
    const int E4 = EDG / 4;
    const int EB4 = (E4 + TB - 1) / TB;

    // ===================== Stage 1 =====================
    init1_kernel<<<256, TB>>>(cnt, newid, NTOT);
    place1_kernel<<<EB4, TB>>>(src4, dst4, cnt, elist, E4);

    matmul64_kernel<<<NTOT / 64, TB>>>(x, W1, nullptr, nullptr, xwh, NTOT, cnt, rdeg);
    conv_kernel<<<(NTOT * 32 + TB - 1) / TB, TB>>>(cnt, elist, rdeg, xwh, b1, p1, h, score, NTOT);

    // topk1: sorts, emits perm/vals/newid, zeroes cnt for stage 2, computes x1
    topk_kernel<<<BG, 1024>>>(score, h, NPG, K1, perm, vals, newid, cnt, x1);

    // ===================== Stage 2 =====================
    place2_kernel<<<EB4, TB>>>(src4, dst4, newid, cnt, elist, E4);

    matmul64_kernel<<<NT1 / 64, TB>>>(h, W2, perm, vals, xwh, NT1, cnt, rdeg);
    conv_kernel<<<(NT1 * 32 + TB - 1) / TB, TB>>>(cnt, elist, rdeg, xwh, b2, p2, h, score, NT1);

    // topk2: only the fused readout output (x2) is consumed downstream
    topk_kernel<<<BG, 1024>>>(score, h, K1, K2,
                              (int*)nullptr, (float*)nullptr, (int*)nullptr, (int*)nullptr, x2);

    // ===================== Head =====================
    head_kernel<<<BG, 64>>>(x1, x2, l1w, l1b, l2w, l2b, out);
}

// round 12
// speedup vs baseline: 1.1186x; 1.0027x over previous
#include <cuda_runtime.h>
#include <cuda_fp16.h>
#include <math.h>

#define BG   64
#define NPG  2048
#define EPG  32768
#define NTOT (BG * NPG)         // 131072
#define EDG  (BG * EPG)         // 2097152
#define K1   1639
#define NT1  (BG * K1)          // 104896 (divisible by 64)
#define K2   1312
#define NT2  (BG * K2)          // 83968
#define DIM  64
#define NCLS 6
#define CAP  64                 // fixed CSR bucket capacity (P(deg>=64) ~ 1e-20)
#define FULLMASK 0xFFFFFFFFu

typedef unsigned long long ull;

// ---------------- scratch ----------------------------------------------------
__device__ __half g_xw[NTOT * DIM];      // (A@W)*rdeg rows, fp16 (halves conv L2 bytes)
__device__ float  g_h[NTOT * DIM];       // conv output (relu'd), fp32
__device__ float  g_score[NTOT];
__device__ float  g_rdeg[NTOT];          // rsqrt(deg incl self-loop)
__device__ int    g_cnt[NTOT];           // in-degree (excl self-loop)
__device__ int    g_elist[NTOT * CAP];   // fixed-stride CSR: src per dst-slot
__device__ int    g_perm[NT1];
__device__ float  g_vals[NT1];
__device__ int    g_newid[NTOT];
__device__ float  g_x1[BG * 2 * DIM];
__device__ float  g_x2[BG * 2 * DIM];

// ---------------- packed f32x2 add (PTX-only; ptxas never auto-emits) --------
__device__ __forceinline__ void add2(ull& d, ull a) {
    asm("add.rn.f32x2 %0, %0, %1;" : "+l"(d) : "l"(a));
}

// ---------------- stage-1 init: cnt=0, newid=-1 ------------------------------
__global__ void init1_kernel(int* __restrict__ cnt, int* __restrict__ newid, int n) {
    int t = blockIdx.x * blockDim.x + threadIdx.x;
    int stride = gridDim.x * blockDim.x;
    for (; t < n; t += stride) { cnt[t] = 0; newid[t] = -1; }
}

// fused count + place, 4 edges/thread via int4 (stage 1: all edges valid)
__global__ void place1_kernel(const int4* __restrict__ src4, const int4* __restrict__ dst4,
                              int* __restrict__ cnt, int* __restrict__ elist, int nedge4) {
    int t = blockIdx.x * blockDim.x + threadIdx.x;
    if (t >= nedge4) return;
    int4 s = src4[t];
    int4 d = dst4[t];
    int slot;
    slot = atomicAdd(&cnt[d.x], 1); elist[d.x * CAP + slot] = s.x;
    slot = atomicAdd(&cnt[d.y], 1); elist[d.y * CAP + slot] = s.y;
    slot = atomicAdd(&cnt[d.z], 1); elist[d.z * CAP + slot] = s.z;
    slot = atomicAdd(&cnt[d.w], 1); elist[d.w * CAP + slot] = s.w;
}

// fused remap + count + place, 4 edges/thread (stage 2)
__global__ void place2_kernel(const int4* __restrict__ src4, const int4* __restrict__ dst4,
                              const int* __restrict__ newid,
                              int* __restrict__ cnt, int* __restrict__ elist, int nedge4) {
    int t = blockIdx.x * blockDim.x + threadIdx.x;
    if (t >= nedge4) return;
    int4 s = src4[t];
    int4 d = dst4[t];
    int s2, d2, slot;
    s2 = newid[s.x]; d2 = newid[d.x];
    if (s2 >= 0 && d2 >= 0) { slot = atomicAdd(&cnt[d2], 1); elist[d2 * CAP + slot] = s2; }
    s2 = newid[s.y]; d2 = newid[d.y];
    if (s2 >= 0 && d2 >= 0) { slot = atomicAdd(&cnt[d2], 1); elist[d2 * CAP + slot] = s2; }
    s2 = newid[s.z]; d2 = newid[d.z];
    if (s2 >= 0 && d2 >= 0) { slot = atomicAdd(&cnt[d2], 1); elist[d2 * CAP + slot] = s2; }
    s2 = newid[s.w]; d2 = newid[d.w];
    if (s2 >= 0 && d2 >= 0) { slot = atomicAdd(&cnt[d2], 1); elist[d2 * CAP + slot] = s2; }
}

// ---------------- GEMM: xw16[i] = fp16( rdeg[i] * (gather(A) @ W)[i] ) -------
// 64-row tile; thread = 4 rows x 4 cols. W repacked as Ws[k4][j][4] ->
// conflict-free LDS128; A reads are broadcasts. Output rows PRE-SCALED by
// rdeg[row] and stored as fp16 (conv reads half the bytes). Also writes rdeg[].
// If perm != nullptr, row i of A is A[perm[i]] * vals[i] (fused TopK gather+gate).
__global__ __launch_bounds__(256, 4) void matmul64_kernel(
    const float* __restrict__ A, const float* __restrict__ W,
    const int* __restrict__ perm, const float* __restrict__ vals,
    __half* __restrict__ C, int nrows,
    const int* __restrict__ cnt, float* __restrict__ rdeg) {
    __shared__ float Ws[16][64][4];   // [k4][col][k-in-group]
    __shared__ float As[64][64];
    int tid = threadIdx.x;
    // rdeg array pass (cnt is final here: GEMM launches after place)
    int gi = blockIdx.x * 256 + tid;
    if (gi < nrows) rdeg[gi] = rsqrtf((float)(cnt[gi] + 1));
    // repack W: W[k][j] row-major -> Ws[k>>2][j][k&3]
    for (int i = tid; i < 4096; i += 256) {
        int k = i >> 6, j = i & 63;
        Ws[k >> 2][j][k & 3] = W[i];
    }
    int row0 = blockIdx.x * 64;
    {
        float4* s4 = (float4*)&As[0][0];
        for (int i = tid; i < 1024; i += 256) {
            int grow = row0 + (i >> 4);       // grow < nrows (nrows % 64 == 0)
            int arow = perm ? perm[grow] : grow;
            float sc = perm ? vals[grow] : 1.0f;
            float4 v = ((const float4*)(A + (size_t)arow * 64))[i & 15];
            v.x *= sc; v.y *= sc; v.z *= sc; v.w *= sc;
            s4[i] = v;
        }
    }
    __syncthreads();
    int tx = tid & 15;    // col base
    int ty = tid >> 4;    // rows ty*4 .. ty*4+3
    float acc[4][4] = {};
#pragma unroll
    for (int k4 = 0; k4 < 16; k4++) {
        float4 w[4];
#pragma unroll
        for (int c = 0; c < 4; c++)
            w[c] = *(const float4*)&Ws[k4][tx + 16 * c][0];
#pragma unroll
        for (int r = 0; r < 4; r++) {
            float4 a = *(const float4*)&As[ty * 4 + r][k4 * 4];
#pragma unroll
            for (int c = 0; c < 4; c++)
                acc[r][c] += a.x * w[c].x + a.y * w[c].y + a.z * w[c].z + a.w * w[c].w;
        }
    }
#pragma unroll
    for (int r = 0; r < 4; r++) {
        int row = row0 + ty * 4 + r;
        float rr = rsqrtf((float)(cnt[row] + 1));
#pragma unroll
        for (int c = 0; c < 4; c++)
            C[(size_t)row * 64 + tx + 16 * c] = __float2half_rn(acc[r][c] * rr);
    }
}

// ---------------- fused CSR-gather conv + epilogue + score -------------------
// One warp per dst node; half-warps process alternate edges. xw rows are fp16
// pre-scaled by rdeg[src]: per edge one LDG.64 per lane (128B/row), converted
// to fp32 and accumulated with packed f32x2 adds. h written fp32.
__global__ __launch_bounds__(256) void conv_kernel(
    const int* __restrict__ cnt, const int* __restrict__ elist,
    const float* __restrict__ rdeg, const __half* __restrict__ xwh,
    const float* __restrict__ bias, const float* __restrict__ p,
    float* __restrict__ h, float* __restrict__ score, int n) {
    int warp = (blockIdx.x * blockDim.x + threadIdx.x) >> 5;
    int lane = threadIdx.x & 31;
    if (warp >= n) return;
    int li   = lane & 15;      // lane covers columns [li*4, li*4+4)
    int half = lane >> 4;
    float rd = rdeg[warp];
    int m = cnt[warp];
    const int* el = elist + (size_t)warp * CAP;
    ull a01 = 0, a23 = 0;      // packed f32x2 accumulators (bits 0 == (0.f,0.f))
    for (int e = half; e < m; e += 2) {
        int s = el[e];
        uint2 hv = *(const uint2*)((const char*)xwh + ((size_t)s << 7) + (li << 3));
        float2 f0 = __half22float2(*(const half2*)&hv.x);
        float2 f1 = __half22float2(*(const half2*)&hv.y);
        add2(a01, *(const ull*)&f0);
        add2(a23, *(const ull*)&f1);
    }
    float2 f01 = *(float2*)&a01;
    float2 f23 = *(float2*)&a23;
    float4 acc = make_float4(f01.x, f01.y, f23.x, f23.y);
    // combine halves (both halves end up with full sums)
    acc.x += __shfl_xor_sync(FULLMASK, acc.x, 16);
    acc.y += __shfl_xor_sync(FULLMASK, acc.y, 16);
    acc.z += __shfl_xor_sync(FULLMASK, acc.z, 16);
    acc.w += __shfl_xor_sync(FULLMASK, acc.w, 16);
    // self-loop term + bias + relu: h = relu(rd*(sum + xw'[dst]) + b)
    uint2 sv = *(const uint2*)((const char*)xwh + ((size_t)warp << 7) + (li << 3));
    float2 s0 = __half22float2(*(const half2*)&sv.x);
    float2 s1 = __half22float2(*(const half2*)&sv.y);
    float4 b4 = ((const float4*)bias)[li];
    acc.x = fmaxf((acc.x + s0.x) * rd + b4.x, 0.f);
    acc.y = fmaxf((acc.y + s0.y) * rd + b4.y, 0.f);
    acc.z = fmaxf((acc.z + s1.x) * rd + b4.z, 0.f);
    acc.w = fmaxf((acc.w + s1.y) * rd + b4.w, 0.f);
    if (half == 0) ((float4*)h)[(size_t)warp * 16 + li] = acc;
    // pooling score: tanh(h.p/||p||). Both halves duplicate -> warp sums are 2x;
    // the 1/sqrt(2) factor corrects dot/sqrt(pp).
    float4 p4 = ((const float4*)p)[li];
    float dot = acc.x * p4.x + acc.y * p4.y + acc.z * p4.z + acc.w * p4.w;
    float pp  = p4.x * p4.x + p4.y * p4.y + p4.z * p4.z + p4.w * p4.w;
#pragma unroll
    for (int o = 16; o; o >>= 1) {
        dot += __shfl_down_sync(FULLMASK, dot, o);
        pp  += __shfl_down_sync(FULLMASK, pp, o);
    }
    if (lane == 0) score[warp] = tanhf(dot * rsqrtf(pp) * 0.7071067811865476f);
}

// ---------------- per-graph top-k (bitonic) + FUSED max/mean readout ---------
// Sorts 2048 keys, emits perm/vals/newid/cnt-zero (optional), then computes
// the [max | mean] readout of the gathered+gated rows directly from the sorted
// keys in smem — replaces the separate maxmean kernel.
__global__ __launch_bounds__(1024) void topk_kernel(
    const float* __restrict__ score, const float* __restrict__ h,
    int n_per, int k,
    int* __restrict__ perm, float* __restrict__ vals, int* __restrict__ newid,
    int* __restrict__ cnt_zero, float* __restrict__ out) {
    __shared__ unsigned long long keys[2048];
    __shared__ float smx[1024], ssm[1024];
    int b = blockIdx.x;
    int tid = threadIdx.x;
    const float* sc = score + (size_t)b * n_per;
#pragma unroll
    for (int i = tid; i < 2048; i += 1024) {
        unsigned long long key;
        if (i < n_per) {
            unsigned u = __float_as_uint(sc[i]);
            u = (u & 0x80000000u) ? ~u : (u | 0x80000000u);
            key = ((unsigned long long)(~u) << 32) | (unsigned)i;
        } else {
            key = 0xFFFFFFFFFFFFFFFFull;
        }
        keys[i] = key;
    }
    __syncthreads();
    for (int kk = 2; kk <= 2048; kk <<= 1) {
        for (int jj = kk >> 1; jj > 0; jj >>= 1) {
#pragma unroll
            for (int i = tid; i < 2048; i += 1024) {
                int ixj = i ^ jj;
                if (ixj > i) {
                    unsigned long long a = keys[i], c = keys[ixj];
                    bool swap = ((i & kk) == 0) ? (a > c) : (a < c);
                    if (swap) { keys[i] = c; keys[ixj] = a; }
                }
            }
            __syncthreads();
        }
    }
    // emit pooling metadata (stage-1 only needs newid/cnt_zero; stage-2 skips)
    for (int r = tid; r < k; r += 1024) {
        int idx = (int)(keys[r] & 0xFFFFFFFFull);
        int g_old = b * n_per + idx;
        if (perm)     perm[b * k + r] = g_old;
        if (vals)     vals[b * k + r] = sc[idx];
        if (newid)    newid[g_old]    = b * k + r;
        if (cnt_zero) cnt_zero[b * k + r] = 0;
    }
    // fused readout: x = [max_r (h[sel_r]*val_r) | mean_r (h[sel_r]*val_r)]
    int j  = tid & 63;
    int rg = tid >> 6;          // 0..15
    float mx = -INFINITY, sum = 0.f;
    for (int r = rg; r < k; r += 16) {
        int idx = (int)(keys[r] & 0xFFFFFFFFull);
        float val = sc[idx];
        float v = h[((size_t)b * n_per + idx) * 64 + j] * val;
        mx = fmaxf(mx, v);
        sum += v;
    }
    smx[tid] = mx;
    ssm[tid] = sum;
    __syncthreads();
    for (int s = 8; s >= 1; s >>= 1) {
        if (rg < s) {
            smx[rg * 64 + j] = fmaxf(smx[rg * 64 + j], smx[(rg + s) * 64 + j]);
            ssm[rg * 64 + j] += ssm[(rg + s) * 64 + j];
        }
        __syncthreads();
    }
    if (rg == 0) {
        out[b * 128 + j]      = smx[j];
        out[b * 128 + 64 + j] = ssm[j] / (float)k;
    }
}

// ---------------- MLP head ---------------------------------------------------
__global__ __launch_bounds__(64) void head_kernel(
    const float* __restrict__ x1, const float* __restrict__ x2,
    const float* __restrict__ l1w, const float* __restrict__ l1b,
    const float* __restrict__ l2w, const float* __restrict__ l2b,
    float* __restrict__ out) {
    int b = blockIdx.x;
    int j = threadIdx.x;
    __shared__ float hv[128];
    __shared__ float h1[64];
    hv[j]      = x1[b * 128 + j]      + x2[b * 128 + j];
    hv[j + 64] = x1[b * 128 + 64 + j] + x2[b * 128 + 64 + j];
    __syncthreads();
    float acc = l1b[j];
#pragma unroll 8
    for (int k = 0; k < 128; k++) acc += hv[k] * l1w[k * 64 + j];
    h1[j] = fmaxf(acc, 0.f);
    __syncthreads();
    if (j < NCLS) {
        float o = l2b[j];
#pragma unroll 8
        for (int kk = 0; kk < 64; kk++) o += h1[kk] * l2w[kk * NCLS + j];
        out[b * NCLS + j] = o;
    }
}

// ---------------- host orchestration ----------------------------------------
extern "C" void kernel_launch(void* const* d_in, const int* in_sizes, int n_in,
                              void* d_out, int out_size) {
    const float* x   = (const float*)d_in[0];
    const int* ei    = (const int*)d_in[1];
    const float* W1  = (const float*)d_in[3];
    const float* b1  = (const float*)d_in[4];
    const float* p1  = (const float*)d_in[5];
    const float* W2  = (const float*)d_in[6];
    const float* b2  = (const float*)d_in[7];
    const float* p2  = (const float*)d_in[8];
    const float* l1w = (const float*)d_in[9];
    const float* l1b = (const float*)d_in[10];
    const float* l2w = (const float*)d_in[11];
    const float* l2b = (const float*)d_in[12];
    float* out = (float*)d_out;

    const int4* src4 = (const int4*)ei;
    const int4* dst4 = (const int4*)(ei + EDG);

    float *h, *score, *rdeg, *vals, *x1, *x2;
    __half* xwh;
    int *cnt, *elist, *perm, *newid;
    cudaGetSymbolAddress((void**)&xwh,    g_xw);
    cudaGetSymbolAddress((void**)&h,      g_h);
    cudaGetSymbolAddress((void**)&score,  g_score);
    cudaGetSymbolAddress((void**)&rdeg,   g_rdeg);
    cudaGetSymbolAddress((void**)&cnt,    g_cnt);
    cudaGetSymbolAddress((void**)&elist,  g_elist);
    cudaGetSymbolAddress((void**)&perm,   g_perm);
    cudaGetSymbolAddress((void**)&newid,  g_newid);
    cudaGetSymbolAddress((void**)&vals,   g_vals);
    cudaGetSymbolAddress((void**)&x1,     g_x1);
    cudaGetSymbolAddress((void**)&x2,     g_x2);

    const int TB = 256;
    const int E4 = EDG / 4;
    const int EB4 = (E4 + TB - 1) / TB;

    // ===================== Stage 1 =====================
    init1_kernel<<<256, TB>>>(cnt, newid, NTOT);
    place1_kernel<<<EB4, TB>>>(src4, dst4, cnt, elist, E4);

    matmul64_kernel<<<NTOT / 64, TB>>>(x, W1, nullptr, nullptr, xwh, NTOT, cnt, rdeg);
    conv_kernel<<<(NTOT * 32 + TB - 1) / TB, TB>>>(cnt, elist, rdeg, xwh, b1, p1, h, score, NTOT);

    // topk1: sorts, emits perm/vals/newid, zeroes cnt for stage 2, computes x1
    topk_kernel<<<BG, 1024>>>(score, h, NPG, K1, perm, vals, newid, cnt, x1);

    // ===================== Stage 2 =====================
    place2_kernel<<<EB4, TB>>>(src4, dst4, newid, cnt, elist, E4);

    matmul64_kernel<<<NT1 / 64, TB>>>(h, W2, perm, vals, xwh, NT1, cnt, rdeg);
    conv_kernel<<<(NT1 * 32 + TB - 1) / TB, TB>>>(cnt, elist, rdeg, xwh, b2, p2, h, score, NT1);

    // topk2: only the fused readout output (x2) is consumed downstream
    topk_kernel<<<BG, 1024>>>(score, h, K1, K2,
                              (int*)nullptr, (float*)nullptr, (int*)nullptr, (int*)nullptr, x2);

    // ===================== Head =====================
    head_kernel<<<BG, 64>>>(x1, x2, l1w, l1b, l2w, l2b, out);
}

// round 13
// speedup vs baseline: 1.2245x; 1.0947x over previous
#include <cuda_runtime.h>
#include <cuda_fp16.h>
#include <math.h>

#define BG   64
#define NPG  2048
#define EPG  32768
#define NTOT (BG * NPG)         // 131072
#define EDG  (BG * EPG)         // 2097152
#define K1   1639
#define NT1  (BG * K1)          // 104896 (divisible by 64)
#define K2   1312
#define NT2  (BG * K2)          // 83968
#define DIM  64
#define NCLS 6
#define CAP  64                 // fixed CSR bucket capacity (P(deg>=64) ~ 1e-20)
#define FULLMASK 0xFFFFFFFFu

typedef unsigned long long ull;

// ---------------- scratch ----------------------------------------------------
__device__ __half g_xw[NTOT * DIM];      // (A@W)*rdeg rows, fp16 (halves conv L2 bytes)
__device__ float  g_h[NTOT * DIM];       // conv output (relu'd), fp32
__device__ float  g_score[NTOT];
__device__ float  g_rdeg[NTOT];          // rsqrt(deg incl self-loop)
__device__ int    g_cnt[NTOT];           // in-degree (excl self-loop)
__device__ int    g_elist[NTOT * CAP];   // fixed-stride CSR: src per dst-slot
__device__ int    g_perm[NT1];
__device__ float  g_vals[NT1];
__device__ int    g_newid[NTOT];
__device__ float  g_x1[BG * 2 * DIM];
__device__ float  g_x2[BG * 2 * DIM];

// ---------------- packed f32x2 add (PTX-only; ptxas never auto-emits) --------
__device__ __forceinline__ void add2(ull& d, ull a) {
    asm("add.rn.f32x2 %0, %0, %1;" : "+l"(d) : "l"(a));
}

// ---------------- stage-1 init: cnt=0, newid=-1 ------------------------------
__global__ void init1_kernel(int* __restrict__ cnt, int* __restrict__ newid, int n) {
    int t = blockIdx.x * blockDim.x + threadIdx.x;
    int stride = gridDim.x * blockDim.x;
    for (; t < n; t += stride) { cnt[t] = 0; newid[t] = -1; }
}

// fused count + place, 4 edges/thread via int4 (stage 1: all edges valid)
__global__ void place1_kernel(const int4* __restrict__ src4, const int4* __restrict__ dst4,
                              int* __restrict__ cnt, int* __restrict__ elist, int nedge4) {
    int t = blockIdx.x * blockDim.x + threadIdx.x;
    if (t >= nedge4) return;
    int4 s = src4[t];
    int4 d = dst4[t];
    int slot;
    slot = atomicAdd(&cnt[d.x], 1); elist[d.x * CAP + slot] = s.x;
    slot = atomicAdd(&cnt[d.y], 1); elist[d.y * CAP + slot] = s.y;
    slot = atomicAdd(&cnt[d.z], 1); elist[d.z * CAP + slot] = s.z;
    slot = atomicAdd(&cnt[d.w], 1); elist[d.w * CAP + slot] = s.w;
}

// fused remap + count + place, 4 edges/thread (stage 2)
__global__ void place2_kernel(const int4* __restrict__ src4, const int4* __restrict__ dst4,
                              const int* __restrict__ newid,
                              int* __restrict__ cnt, int* __restrict__ elist, int nedge4) {
    int t = blockIdx.x * blockDim.x + threadIdx.x;
    if (t >= nedge4) return;
    int4 s = src4[t];
    int4 d = dst4[t];
    int s2, d2, slot;
    s2 = newid[s.x]; d2 = newid[d.x];
    if (s2 >= 0 && d2 >= 0) { slot = atomicAdd(&cnt[d2], 1); elist[d2 * CAP + slot] = s2; }
    s2 = newid[s.y]; d2 = newid[d.y];
    if (s2 >= 0 && d2 >= 0) { slot = atomicAdd(&cnt[d2], 1); elist[d2 * CAP + slot] = s2; }
    s2 = newid[s.z]; d2 = newid[d.z];
    if (s2 >= 0 && d2 >= 0) { slot = atomicAdd(&cnt[d2], 1); elist[d2 * CAP + slot] = s2; }
    s2 = newid[s.w]; d2 = newid[d.w];
    if (s2 >= 0 && d2 >= 0) { slot = atomicAdd(&cnt[d2], 1); elist[d2 * CAP + slot] = s2; }
}

// ---------------- GEMM: xw16[i] = fp16( rdeg[i] * (gather(A) @ W)[i] ) -------
// 64-row tile; thread = 4 rows x 4 cols. W repacked as Ws[k4][j][4] ->
// conflict-free LDS128; A reads are broadcasts. Output rows PRE-SCALED by
// rdeg[row] and stored as fp16 (conv reads half the bytes). Also writes rdeg[].
// If perm != nullptr, row i of A is A[perm[i]] * vals[i] (fused TopK gather+gate).
__global__ __launch_bounds__(256, 4) void matmul64_kernel(
    const float* __restrict__ A, const float* __restrict__ W,
    const int* __restrict__ perm, const float* __restrict__ vals,
    __half* __restrict__ C, int nrows,
    const int* __restrict__ cnt, float* __restrict__ rdeg) {
    __shared__ float Ws[16][64][4];   // [k4][col][k-in-group]
    __shared__ float As[64][64];
    int tid = threadIdx.x;
    // rdeg array pass (cnt is final here: GEMM launches after place)
    int gi = blockIdx.x * 256 + tid;
    if (gi < nrows) rdeg[gi] = rsqrtf((float)(cnt[gi] + 1));
    // repack W: W[k][j] row-major -> Ws[k>>2][j][k&3]
    for (int i = tid; i < 4096; i += 256) {
        int k = i >> 6, j = i & 63;
        Ws[k >> 2][j][k & 3] = W[i];
    }
    int row0 = blockIdx.x * 64;
    {
        float4* s4 = (float4*)&As[0][0];
        for (int i = tid; i < 1024; i += 256) {
            int grow = row0 + (i >> 4);       // grow < nrows (nrows % 64 == 0)
            int arow = perm ? perm[grow] : grow;
            float sc = perm ? vals[grow] : 1.0f;
            float4 v = ((const float4*)(A + (size_t)arow * 64))[i & 15];
            v.x *= sc; v.y *= sc; v.z *= sc; v.w *= sc;
            s4[i] = v;
        }
    }
    __syncthreads();
    int tx = tid & 15;    // col base
    int ty = tid >> 4;    // rows ty*4 .. ty*4+3
    float acc[4][4] = {};
#pragma unroll
    for (int k4 = 0; k4 < 16; k4++) {
        float4 w[4];
#pragma unroll
        for (int c = 0; c < 4; c++)
            w[c] = *(const float4*)&Ws[k4][tx + 16 * c][0];
#pragma unroll
        for (int r = 0; r < 4; r++) {
            float4 a = *(const float4*)&As[ty * 4 + r][k4 * 4];
#pragma unroll
            for (int c = 0; c < 4; c++)
                acc[r][c] += a.x * w[c].x + a.y * w[c].y + a.z * w[c].z + a.w * w[c].w;
        }
    }
#pragma unroll
    for (int r = 0; r < 4; r++) {
        int row = row0 + ty * 4 + r;
        float rr = rsqrtf((float)(cnt[row] + 1));
#pragma unroll
        for (int c = 0; c < 4; c++)
            C[(size_t)row * 64 + tx + 16 * c] = __float2half_rn(acc[r][c] * rr);
    }
}

// ---------------- fused CSR-gather conv + epilogue + score -------------------
// One warp per dst node; half-warps process alternate edges. xw rows are fp16
// pre-scaled by rdeg[src]: per edge one LDG.64 per lane (128B/row), converted
// to fp32 and accumulated with packed f32x2 adds. h written fp32.
__global__ __launch_bounds__(256) void conv_kernel(
    const int* __restrict__ cnt, const int* __restrict__ elist,
    const float* __restrict__ rdeg, const __half* __restrict__ xwh,
    const float* __restrict__ bias, const float* __restrict__ p,
    float* __restrict__ h, float* __restrict__ score, int n) {
    int warp = (blockIdx.x * blockDim.x + threadIdx.x) >> 5;
    int lane = threadIdx.x & 31;
    if (warp >= n) return;
    int li   = lane & 15;      // lane covers columns [li*4, li*4+4)
    int half = lane >> 4;
    float rd = rdeg[warp];
    int m = cnt[warp];
    const int* el = elist + (size_t)warp * CAP;
    ull a01 = 0, a23 = 0;      // packed f32x2 accumulators (bits 0 == (0.f,0.f))
    for (int e = half; e < m; e += 2) {
        int s = el[e];
        uint2 hv = *(const uint2*)((const char*)xwh + ((size_t)s << 7) + (li << 3));
        float2 f0 = __half22float2(*(const half2*)&hv.x);
        float2 f1 = __half22float2(*(const half2*)&hv.y);
        add2(a01, *(const ull*)&f0);
        add2(a23, *(const ull*)&f1);
    }
    float2 f01 = *(float2*)&a01;
    float2 f23 = *(float2*)&a23;
    float4 acc = make_float4(f01.x, f01.y, f23.x, f23.y);
    // combine halves (both halves end up with full sums)
    acc.x += __shfl_xor_sync(FULLMASK, acc.x, 16);
    acc.y += __shfl_xor_sync(FULLMASK, acc.y, 16);
    acc.z += __shfl_xor_sync(FULLMASK, acc.z, 16);
    acc.w += __shfl_xor_sync(FULLMASK, acc.w, 16);
    // self-loop term + bias + relu: h = relu(rd*(sum + xw'[dst]) + b)
    uint2 sv = *(const uint2*)((const char*)xwh + ((size_t)warp << 7) + (li << 3));
    float2 s0 = __half22float2(*(const half2*)&sv.x);
    float2 s1 = __half22float2(*(const half2*)&sv.y);
    float4 b4 = ((const float4*)bias)[li];
    acc.x = fmaxf((acc.x + s0.x) * rd + b4.x, 0.f);
    acc.y = fmaxf((acc.y + s0.y) * rd + b4.y, 0.f);
    acc.z = fmaxf((acc.z + s1.x) * rd + b4.z, 0.f);
    acc.w = fmaxf((acc.w + s1.y) * rd + b4.w, 0.f);
    if (half == 0) ((float4*)h)[(size_t)warp * 16 + li] = acc;
    // pooling score: tanh(h.p/||p||). Both halves duplicate -> warp sums are 2x;
    // the 1/sqrt(2) factor corrects dot/sqrt(pp).
    float4 p4 = ((const float4*)p)[li];
    float dot = acc.x * p4.x + acc.y * p4.y + acc.z * p4.z + acc.w * p4.w;
    float pp  = p4.x * p4.x + p4.y * p4.y + p4.z * p4.z + p4.w * p4.w;
#pragma unroll
    for (int o = 16; o; o >>= 1) {
        dot += __shfl_down_sync(FULLMASK, dot, o);
        pp  += __shfl_down_sync(FULLMASK, pp, o);
    }
    if (lane == 0) score[warp] = tanhf(dot * rsqrtf(pp) * 0.7071067811865476f);
}

// ---------------- per-graph top-k via EXACT RADIX-SELECT + fused readout -----
// Selection set matches jax top_k exactly (top-k by value, lowest-index
// tie-break; ties are real: tanhf saturates to +-1.0). Selected order is
// arbitrary — everything downstream (relabeled stage-2 graph, max/mean
// readouts, logits) is permutation-invariant.
__global__ __launch_bounds__(1024) void topk_kernel(
    const float* __restrict__ score, const float* __restrict__ h,
    int n_per, int k,
    int* __restrict__ perm, float* __restrict__ vals, int* __restrict__ newid,
    int* __restrict__ cnt_zero, float* __restrict__ out) {
    __shared__ unsigned keys[2048];
    __shared__ int sel[2048];
    __shared__ int hist[256];
    __shared__ int sbuf[1024];
    __shared__ float smx[1024], ssm[1024];
    __shared__ int s_thr, s_kRem, s_ctr;
    int b = blockIdx.x;
    int tid = threadIdx.x;
    const float* sc = score + (size_t)b * n_per;
    // monotone map float -> u32 (ascending); padding = 0 (< any real key)
    for (int i = tid; i < 2048; i += 1024) {
        unsigned u = 0;
        if (i < n_per) {
            u = __float_as_uint(sc[i]);
            u = (u & 0x80000000u) ? ~u : (u | 0x80000000u);
        }
        keys[i] = u;
    }
    // ---- 4-pass radix: find T = k-th largest key, kRem = #needed among ==T
    unsigned pfx = 0, pfxMask = 0;
    int kRem = k;
    for (int shift = 24; shift >= 0; shift -= 8) {
        if (tid < 256) hist[tid] = 0;
        __syncthreads();
        for (int i = tid; i < 2048; i += 1024) {
            unsigned u = keys[i];
            if ((u & pfxMask) == pfx) atomicAdd(&hist[(u >> shift) & 255u], 1);
        }
        __syncthreads();
        // suffix sums via reversed inclusive scan (threads 0..255)
        if (tid < 256) sbuf[tid] = hist[255 - tid];
        __syncthreads();
        for (int off = 1; off < 256; off <<= 1) {
            int t = (tid < 256 && tid >= off) ? sbuf[tid - off] : 0;
            __syncthreads();
            if (tid < 256) sbuf[tid] += t;
            __syncthreads();
        }
        if (tid < 256) {
            int x = 255 - tid;
            int sInc = sbuf[tid];          // #keys in class with byte >= x
            int sExc = sInc - hist[x];     // #keys in class with byte >  x
            if (sExc < kRem && kRem <= sInc) { s_thr = x; s_kRem = kRem - sExc; }
        }
        __syncthreads();
        pfx |= ((unsigned)s_thr) << shift;
        pfxMask |= 255u << shift;
        kRem = s_kRem;
        __syncthreads();
    }
    unsigned T = pfx;
    int base = k - kRem;                   // #keys strictly greater than T
    // ---- select keys > T (arbitrary order)
    if (tid == 0) s_ctr = 0;
    __syncthreads();
    for (int i = tid; i < n_per; i += 1024) {
        if (keys[i] > T) { int pos = atomicAdd(&s_ctr, 1); sel[pos] = i; }
    }
    __syncthreads();
    // ---- ties at T: take kRem lowest indices (stable block scan, 2 elems/thr)
    int i0 = 2 * tid, i1 = 2 * tid + 1;
    int e0 = (i0 < n_per) && (keys[i0] == T);
    int e1 = (i1 < n_per) && (keys[i1] == T);
    sbuf[tid] = e0 + e1;
    __syncthreads();
    for (int off = 1; off < 1024; off <<= 1) {
        int t = (tid >= off) ? sbuf[tid - off] : 0;
        __syncthreads();
        sbuf[tid] += t;
        __syncthreads();
    }
    int pre = sbuf[tid] - (e0 + e1);       // exclusive prefix (index order)
    if (e0 && pre < kRem)       sel[base + pre]       = i0;
    if (e1 && pre + e0 < kRem)  sel[base + pre + e0]  = i1;
    __syncthreads();
    // ---- emit pooling metadata (stage-2 passes nulls)
    for (int r = tid; r < k; r += 1024) {
        int idx = sel[r];
        if (perm)     perm[b * k + r] = b * n_per + idx;
        if (vals)     vals[b * k + r] = sc[idx];
        if (newid)    newid[b * n_per + idx] = b * k + r;
        if (cnt_zero) cnt_zero[b * k + r] = 0;
    }
    // ---- fused readout: x = [max_r (h[sel_r]*val_r) | mean_r (h[sel_r]*val_r)]
    int j  = tid & 63;
    int rg = tid >> 6;          // 0..15
    float mx = -INFINITY, sum = 0.f;
    for (int r = rg; r < k; r += 16) {
        int idx = sel[r];
        float val = sc[idx];
        float v = h[((size_t)b * n_per + idx) * 64 + j] * val;
        mx = fmaxf(mx, v);
        sum += v;
    }
    smx[tid] = mx;
    ssm[tid] = sum;
    __syncthreads();
    for (int s = 8; s >= 1; s >>= 1) {
        if (rg < s) {
            smx[rg * 64 + j] = fmaxf(smx[rg * 64 + j], smx[(rg + s) * 64 + j]);
            ssm[rg * 64 + j] += ssm[(rg + s) * 64 + j];
        }
        __syncthreads();
    }
    if (rg == 0) {
        out[b * 128 + j]      = smx[j];
        out[b * 128 + 64 + j] = ssm[j] / (float)k;
    }
}

// ---------------- MLP head ---------------------------------------------------
__global__ __launch_bounds__(64) void head_kernel(
    const float* __restrict__ x1, const float* __restrict__ x2,
    const float* __restrict__ l1w, const float* __restrict__ l1b,
    const float* __restrict__ l2w, const float* __restrict__ l2b,
    float* __restrict__ out) {
    int b = blockIdx.x;
    int j = threadIdx.x;
    __shared__ float hv[128];
    __shared__ float h1[64];
    hv[j]      = x1[b * 128 + j]      + x2[b * 128 + j];
    hv[j + 64] = x1[b * 128 + 64 + j] + x2[b * 128 + 64 + j];
    __syncthreads();
    float acc = l1b[j];
#pragma unroll 8
    for (int k = 0; k < 128; k++) acc += hv[k] * l1w[k * 64 + j];
    h1[j] = fmaxf(acc, 0.f);
    __syncthreads();
    if (j < NCLS) {
        float o = l2b[j];
#pragma unroll 8
        for (int kk = 0; kk < 64; kk++) o += h1[kk] * l2w[kk * NCLS + j];
        out[b * NCLS + j] = o;
    }
}

// ---------------- host orchestration ----------------------------------------
extern "C" void kernel_launch(void* const* d_in, const int* in_sizes, int n_in,
                              void* d_out, int out_size) {
    const float* x   = (const float*)d_in[0];
    const int* ei    = (const int*)d_in[1];
    const float* W1  = (const float*)d_in[3];
    const float* b1  = (const float*)d_in[4];
    const float* p1  = (const float*)d_in[5];
    const float* W2  = (const float*)d_in[6];
    const float* b2  = (const float*)d_in[7];
    const float* p2  = (const float*)d_in[8];
    const float* l1w = (const float*)d_in[9];
    const float* l1b = (const float*)d_in[10];
    const float* l2w = (const float*)d_in[11];
    const float* l2b = (const float*)d_in[12];
    float* out = (float*)d_out;

    const int4* src4 = (const int4*)ei;
    const int4* dst4 = (const int4*)(ei + EDG);

    float *h, *score, *rdeg, *vals, *x1, *x2;
    __half* xwh;
    int *cnt, *elist, *perm, *newid;
    cudaGetSymbolAddress((void**)&xwh,    g_xw);
    cudaGetSymbolAddress((void**)&h,      g_h);
    cudaGetSymbolAddress((void**)&score,  g_score);
    cudaGetSymbolAddress((void**)&rdeg,   g_rdeg);
    cudaGetSymbolAddress((void**)&cnt,    g_cnt);
    cudaGetSymbolAddress((void**)&elist,  g_elist);
    cudaGetSymbolAddress((void**)&perm,   g_perm);
    cudaGetSymbolAddress((void**)&newid,  g_newid);
    cudaGetSymbolAddress((void**)&vals,   g_vals);
    cudaGetSymbolAddress((void**)&x1,     g_x1);
    cudaGetSymbolAddress((void**)&x2,     g_x2);

    const int TB = 256;
    const int E4 = EDG / 4;
    const int EB4 = (E4 + TB - 1) / TB;

    // ===================== Stage 1 =====================
    init1_kernel<<<256, TB>>>(cnt, newid, NTOT);
    place1_kernel<<<EB4, TB>>>(src4, dst4, cnt, elist, E4);

    matmul64_kernel<<<NTOT / 64, TB>>>(x, W1, nullptr, nullptr, xwh, NTOT, cnt, rdeg);
    conv_kernel<<<(NTOT * 32 + TB - 1) / TB, TB>>>(cnt, elist, rdeg, xwh, b1, p1, h, score, NTOT);

    // topk1: radix-selects, emits perm/vals/newid, zeroes cnt for stage 2, computes x1
    topk_kernel<<<BG, 1024>>>(score, h, NPG, K1, perm, vals, newid, cnt, x1);

    // ===================== Stage 2 =====================
    place2_kernel<<<EB4, TB>>>(src4, dst4, newid, cnt, elist, E4);

    matmul64_kernel<<<NT1 / 64, TB>>>(h, W2, perm, vals, xwh, NT1, cnt, rdeg);
    conv_kernel<<<(NT1 * 32 + TB - 1) / TB, TB>>>(cnt, elist, rdeg, xwh, b2, p2, h, score, NT1);

    // topk2: only the fused readout output (x2) is consumed downstream
    topk_kernel<<<BG, 1024>>>(score, h, K1, K2,
                              (int*)nullptr, (float*)nullptr, (int*)nullptr, (int*)nullptr, x2);

    // ===================== Head =====================
    head_kernel<<<BG, 64>>>(x1, x2, l1w, l1b, l2w, l2b, out);
}

// round 14
// speedup vs baseline: 1.2393x; 1.0120x over previous
#include <cuda_runtime.h>
#include <cuda_fp16.h>
#include <math.h>

#define BG   64
#define NPG  2048
#define EPG  32768
#define NTOT (BG * NPG)         // 131072
#define EDG  (BG * EPG)         // 2097152
#define K1   1639
#define NT1  (BG * K1)          // 104896 (divisible by 64)
#define K2   1312
#define NT2  (BG * K2)          // 83968
#define DIM  64
#define NCLS 6
#define CAP  64                 // fixed CSR bucket capacity (P(deg>=64) ~ 1e-20)
#define FULLMASK 0xFFFFFFFFu

typedef unsigned long long ull;

// ---------------- scratch ----------------------------------------------------
__device__ __half g_xw[NTOT * DIM];      // (A@W)*rdeg rows, fp16 (halves conv L2 bytes)
__device__ float  g_h[NTOT * DIM];       // conv output (relu'd), fp32
__device__ float  g_score[NTOT];
__device__ float  g_rdeg[NTOT];          // rsqrt(deg incl self-loop)
__device__ int    g_cnt[NTOT];           // in-degree (excl self-loop)
__device__ int    g_elist[NTOT * CAP];   // fixed-stride CSR: src per dst-slot
__device__ int    g_perm[NT1];
__device__ float  g_vals[NT1];
__device__ int    g_newid[NTOT];
__device__ float  g_x1[BG * 2 * DIM];
__device__ float  g_x2[BG * 2 * DIM];

// ---------------- packed f32x2 add (PTX-only; ptxas never auto-emits) --------
__device__ __forceinline__ void add2(ull& d, ull a) {
    asm("add.rn.f32x2 %0, %0, %1;" : "+l"(d) : "l"(a));
}

// ---------------- stage-1 init: cnt=0, newid=-1 ------------------------------
__global__ void init1_kernel(int* __restrict__ cnt, int* __restrict__ newid, int n) {
    int t = blockIdx.x * blockDim.x + threadIdx.x;
    int stride = gridDim.x * blockDim.x;
    for (; t < n; t += stride) { cnt[t] = 0; newid[t] = -1; }
}

// fused count + place, 4 edges/thread via int4 (stage 1: all edges valid)
__global__ void place1_kernel(const int4* __restrict__ src4, const int4* __restrict__ dst4,
                              int* __restrict__ cnt, int* __restrict__ elist, int nedge4) {
    int t = blockIdx.x * blockDim.x + threadIdx.x;
    if (t >= nedge4) return;
    int4 s = src4[t];
    int4 d = dst4[t];
    int slot;
    slot = atomicAdd(&cnt[d.x], 1); elist[d.x * CAP + slot] = s.x;
    slot = atomicAdd(&cnt[d.y], 1); elist[d.y * CAP + slot] = s.y;
    slot = atomicAdd(&cnt[d.z], 1); elist[d.z * CAP + slot] = s.z;
    slot = atomicAdd(&cnt[d.w], 1); elist[d.w * CAP + slot] = s.w;
}

// fused remap + count + place, 4 edges/thread (stage 2)
__global__ void place2_kernel(const int4* __restrict__ src4, const int4* __restrict__ dst4,
                              const int* __restrict__ newid,
                              int* __restrict__ cnt, int* __restrict__ elist, int nedge4) {
    int t = blockIdx.x * blockDim.x + threadIdx.x;
    if (t >= nedge4) return;
    int4 s = src4[t];
    int4 d = dst4[t];
    int s2, d2, slot;
    s2 = newid[s.x]; d2 = newid[d.x];
    if (s2 >= 0 && d2 >= 0) { slot = atomicAdd(&cnt[d2], 1); elist[d2 * CAP + slot] = s2; }
    s2 = newid[s.y]; d2 = newid[d.y];
    if (s2 >= 0 && d2 >= 0) { slot = atomicAdd(&cnt[d2], 1); elist[d2 * CAP + slot] = s2; }
    s2 = newid[s.z]; d2 = newid[d.z];
    if (s2 >= 0 && d2 >= 0) { slot = atomicAdd(&cnt[d2], 1); elist[d2 * CAP + slot] = s2; }
    s2 = newid[s.w]; d2 = newid[d.w];
    if (s2 >= 0 && d2 >= 0) { slot = atomicAdd(&cnt[d2], 1); elist[d2 * CAP + slot] = s2; }
}

// ---------------- GEMM: xw16[i] = fp16( rdeg[i] * (gather(A) @ W)[i] ) -------
// 64-row tile; thread = 4 rows x 4 cols. W repacked as Ws[k4][j][4] ->
// conflict-free LDS128; A reads are broadcasts. Output rows PRE-SCALED by
// rdeg[row] and stored as fp16 (conv reads half the bytes). Also writes rdeg[].
// If perm != nullptr, row i of A is A[perm[i]] * vals[i] (fused TopK gather+gate).
__global__ __launch_bounds__(256, 4) void matmul64_kernel(
    const float* __restrict__ A, const float* __restrict__ W,
    const int* __restrict__ perm, const float* __restrict__ vals,
    __half* __restrict__ C, int nrows,
    const int* __restrict__ cnt, float* __restrict__ rdeg) {
    __shared__ float Ws[16][64][4];   // [k4][col][k-in-group]
    __shared__ float As[64][64];
    int tid = threadIdx.x;
    // rdeg array pass (cnt is final here: GEMM launches after place)
    int gi = blockIdx.x * 256 + tid;
    if (gi < nrows) rdeg[gi] = rsqrtf((float)(cnt[gi] + 1));
    // repack W: W[k][j] row-major -> Ws[k>>2][j][k&3]
    for (int i = tid; i < 4096; i += 256) {
        int k = i >> 6, j = i & 63;
        Ws[k >> 2][j][k & 3] = W[i];
    }
    int row0 = blockIdx.x * 64;
    {
        float4* s4 = (float4*)&As[0][0];
        for (int i = tid; i < 1024; i += 256) {
            int grow = row0 + (i >> 4);       // grow < nrows (nrows % 64 == 0)
            int arow = perm ? perm[grow] : grow;
            float sc = perm ? vals[grow] : 1.0f;
            float4 v = ((const float4*)(A + (size_t)arow * 64))[i & 15];
            v.x *= sc; v.y *= sc; v.z *= sc; v.w *= sc;
            s4[i] = v;
        }
    }
    __syncthreads();
    int tx = tid & 15;    // col base
    int ty = tid >> 4;    // rows ty*4 .. ty*4+3
    float acc[4][4] = {};
#pragma unroll
    for (int k4 = 0; k4 < 16; k4++) {
        float4 w[4];
#pragma unroll
        for (int c = 0; c < 4; c++)
            w[c] = *(const float4*)&Ws[k4][tx + 16 * c][0];
#pragma unroll
        for (int r = 0; r < 4; r++) {
            float4 a = *(const float4*)&As[ty * 4 + r][k4 * 4];
#pragma unroll
            for (int c = 0; c < 4; c++)
                acc[r][c] += a.x * w[c].x + a.y * w[c].y + a.z * w[c].z + a.w * w[c].w;
        }
    }
#pragma unroll
    for (int r = 0; r < 4; r++) {
        int row = row0 + ty * 4 + r;
        float rr = rsqrtf((float)(cnt[row] + 1));
#pragma unroll
        for (int c = 0; c < 4; c++)
            C[(size_t)row * 64 + tx + 16 * c] = __float2half_rn(acc[r][c] * rr);
    }
}

// ---------------- fused CSR-gather conv + epilogue + score -------------------
// One warp per dst node; half-warps process alternate edges IN PAIRS:
// two fp16 row slices are combined with HADD2 (one fp16 rounding per pair),
// then converted once and accumulated in fp32 via packed f32x2 adds.
// ~4.2 instr/edge vs 5.5 before. No sync primitives in divergent code.
__global__ __launch_bounds__(256) void conv_kernel(
    const int* __restrict__ cnt, const int* __restrict__ elist,
    const float* __restrict__ rdeg, const __half* __restrict__ xwh,
    const float* __restrict__ bias, const float* __restrict__ p,
    float* __restrict__ h, float* __restrict__ score, int n) {
    int warp = (blockIdx.x * blockDim.x + threadIdx.x) >> 5;
    int lane = threadIdx.x & 31;
    if (warp >= n) return;
    int li   = lane & 15;      // lane covers columns [li*4, li*4+4)
    int half = lane >> 4;
    float rd = rdeg[warp];
    int m = cnt[warp];
    const int* el = elist + (size_t)warp * CAP;
    ull a01 = 0, a23 = 0;      // packed f32x2 accumulators (bits 0 == (0.f,0.f))
    int e = half;
#pragma unroll 2
    for (; e + 2 < m; e += 4) {
        int s0 = el[e], s1 = el[e + 2];
        uint2 v0 = *(const uint2*)((const char*)xwh + ((size_t)s0 << 7) + (li << 3));
        uint2 v1 = *(const uint2*)((const char*)xwh + ((size_t)s1 << 7) + (li << 3));
        __half2 pA = __hadd2(*(const __half2*)&v0.x, *(const __half2*)&v1.x);
        __half2 pB = __hadd2(*(const __half2*)&v0.y, *(const __half2*)&v1.y);
        float2 f0 = __half22float2(pA);
        float2 f1 = __half22float2(pB);
        add2(a01, *(const ull*)&f0);
        add2(a23, *(const ull*)&f1);
    }
    if (e < m) {               // at most one tail edge per half
        int s = el[e];
        uint2 hv = *(const uint2*)((const char*)xwh + ((size_t)s << 7) + (li << 3));
        float2 f0 = __half22float2(*(const __half2*)&hv.x);
        float2 f1 = __half22float2(*(const __half2*)&hv.y);
        add2(a01, *(const ull*)&f0);
        add2(a23, *(const ull*)&f1);
    }
    float2 f01 = *(float2*)&a01;
    float2 f23 = *(float2*)&a23;
    float4 acc = make_float4(f01.x, f01.y, f23.x, f23.y);
    // combine halves (both halves end up with full sums)
    acc.x += __shfl_xor_sync(FULLMASK, acc.x, 16);
    acc.y += __shfl_xor_sync(FULLMASK, acc.y, 16);
    acc.z += __shfl_xor_sync(FULLMASK, acc.z, 16);
    acc.w += __shfl_xor_sync(FULLMASK, acc.w, 16);
    // self-loop term + bias + relu: h = relu(rd*(sum + xw'[dst]) + b)
    uint2 sv = *(const uint2*)((const char*)xwh + ((size_t)warp << 7) + (li << 3));
    float2 s0 = __half22float2(*(const __half2*)&sv.x);
    float2 s1 = __half22float2(*(const __half2*)&sv.y);
    float4 b4 = ((const float4*)bias)[li];
    acc.x = fmaxf((acc.x + s0.x) * rd + b4.x, 0.f);
    acc.y = fmaxf((acc.y + s0.y) * rd + b4.y, 0.f);
    acc.z = fmaxf((acc.z + s1.x) * rd + b4.z, 0.f);
    acc.w = fmaxf((acc.w + s1.y) * rd + b4.w, 0.f);
    if (half == 0) ((float4*)h)[(size_t)warp * 16 + li] = acc;
    // pooling score: tanh(h.p/||p||). Both halves duplicate -> warp sums are 2x;
    // the 1/sqrt(2) factor corrects dot/sqrt(pp).
    float4 p4 = ((const float4*)p)[li];
    float dot = acc.x * p4.x + acc.y * p4.y + acc.z * p4.z + acc.w * p4.w;
    float pp  = p4.x * p4.x + p4.y * p4.y + p4.z * p4.z + p4.w * p4.w;
#pragma unroll
    for (int o = 16; o; o >>= 1) {
        dot += __shfl_down_sync(FULLMASK, dot, o);
        pp  += __shfl_down_sync(FULLMASK, pp, o);
    }
    if (lane == 0) score[warp] = tanhf(dot * rsqrtf(pp) * 0.7071067811865476f);
}

// ---------------- per-graph top-k via EXACT RADIX-SELECT + fused readout -----
// Selection set matches jax top_k exactly (top-k by value, lowest-index
// tie-break). Selected order is arbitrary — downstream is permutation-invariant.
__global__ __launch_bounds__(1024) void topk_kernel(
    const float* __restrict__ score, const float* __restrict__ h,
    int n_per, int k,
    int* __restrict__ perm, float* __restrict__ vals, int* __restrict__ newid,
    int* __restrict__ cnt_zero, float* __restrict__ out) {
    __shared__ unsigned keys[2048];
    __shared__ int sel[2048];
    __shared__ int hist[256];
    __shared__ int sbuf[1024];
    __shared__ float smx[1024], ssm[1024];
    __shared__ int s_thr, s_kRem, s_ctr;
    int b = blockIdx.x;
    int tid = threadIdx.x;
    const float* sc = score + (size_t)b * n_per;
    // monotone map float -> u32 (ascending); padding = 0 (< any real key)
    for (int i = tid; i < 2048; i += 1024) {
        unsigned u = 0;
        if (i < n_per) {
            u = __float_as_uint(sc[i]);
            u = (u & 0x80000000u) ? ~u : (u | 0x80000000u);
        }
        keys[i] = u;
    }
    // ---- 4-pass radix: find T = k-th largest key, kRem = #needed among ==T
    unsigned pfx = 0, pfxMask = 0;
    int kRem = k;
    for (int shift = 24; shift >= 0; shift -= 8) {
        if (tid < 256) hist[tid] = 0;
        __syncthreads();
        for (int i = tid; i < 2048; i += 1024) {
            unsigned u = keys[i];
            if ((u & pfxMask) == pfx) atomicAdd(&hist[(u >> shift) & 255u], 1);
        }
        __syncthreads();
        // suffix sums via reversed inclusive scan (threads 0..255)
        if (tid < 256) sbuf[tid] = hist[255 - tid];
        __syncthreads();
        for (int off = 1; off < 256; off <<= 1) {
            int t = (tid < 256 && tid >= off) ? sbuf[tid - off] : 0;
            __syncthreads();
            if (tid < 256) sbuf[tid] += t;
            __syncthreads();
        }
        if (tid < 256) {
            int x = 255 - tid;
            int sInc = sbuf[tid];          // #keys in class with byte >= x
            int sExc = sInc - hist[x];     // #keys in class with byte >  x
            if (sExc < kRem && kRem <= sInc) { s_thr = x; s_kRem = kRem - sExc; }
        }
        __syncthreads();
        pfx |= ((unsigned)s_thr) << shift;
        pfxMask |= 255u << shift;
        kRem = s_kRem;
        __syncthreads();
    }
    unsigned T = pfx;
    int base = k - kRem;                   // #keys strictly greater than T
    // ---- select keys > T (arbitrary order)
    if (tid == 0) s_ctr = 0;
    __syncthreads();
    for (int i = tid; i < n_per; i += 1024) {
        if (keys[i] > T) { int pos = atomicAdd(&s_ctr, 1); sel[pos] = i; }
    }
    __syncthreads();
    // ---- ties at T: take kRem lowest indices (stable block scan, 2 elems/thr)
    int i0 = 2 * tid, i1 = 2 * tid + 1;
    int e0 = (i0 < n_per) && (keys[i0] == T);
    int e1 = (i1 < n_per) && (keys[i1] == T);
    sbuf[tid] = e0 + e1;
    __syncthreads();
    for (int off = 1; off < 1024; off <<= 1) {
        int t = (tid >= off) ? sbuf[tid - off] : 0;
        __syncthreads();
        sbuf[tid] += t;
        __syncthreads();
    }
    int pre = sbuf[tid] - (e0 + e1);       // exclusive prefix (index order)
    if (e0 && pre < kRem)       sel[base + pre]       = i0;
    if (e1 && pre + e0 < kRem)  sel[base + pre + e0]  = i1;
    __syncthreads();
    // ---- emit pooling metadata (stage-2 passes nulls)
    for (int r = tid; r < k; r += 1024) {
        int idx = sel[r];
        if (perm)     perm[b * k + r] = b * n_per + idx;
        if (vals)     vals[b * k + r] = sc[idx];
        if (newid)    newid[b * n_per + idx] = b * k + r;
        if (cnt_zero) cnt_zero[b * k + r] = 0;
    }
    // ---- fused readout: x = [max_r (h[sel_r]*val_r) | mean_r (h[sel_r]*val_r)]
    int j  = tid & 63;
    int rg = tid >> 6;          // 0..15
    float mx = -INFINITY, sum = 0.f;
    for (int r = rg; r < k; r += 16) {
        int idx = sel[r];
        float val = sc[idx];
        float v = h[((size_t)b * n_per + idx) * 64 + j] * val;
        mx = fmaxf(mx, v);
        sum += v;
    }
    smx[tid] = mx;
    ssm[tid] = sum;
    __syncthreads();
    for (int s = 8; s >= 1; s >>= 1) {
        if (rg < s) {
            smx[rg * 64 + j] = fmaxf(smx[rg * 64 + j], smx[(rg + s) * 64 + j]);
            ssm[rg * 64 + j] += ssm[(rg + s) * 64 + j];
        }
        __syncthreads();
    }
    if (rg == 0) {
        out[b * 128 + j]      = smx[j];
        out[b * 128 + 64 + j] = ssm[j] / (float)k;
    }
}

// ---------------- MLP head ---------------------------------------------------
__global__ __launch_bounds__(64) void head_kernel(
    const float* __restrict__ x1, const float* __restrict__ x2,
    const float* __restrict__ l1w, const float* __restrict__ l1b,
    const float* __restrict__ l2w, const float* __restrict__ l2b,
    float* __restrict__ out) {
    int b = blockIdx.x;
    int j = threadIdx.x;
    __shared__ float hv[128];
    __shared__ float h1[64];
    hv[j]      = x1[b * 128 + j]      + x2[b * 128 + j];
    hv[j + 64] = x1[b * 128 + 64 + j] + x2[b * 128 + 64 + j];
    __syncthreads();
    float acc = l1b[j];
#pragma unroll 8
    for (int k = 0; k < 128; k++) acc += hv[k] * l1w[k * 64 + j];
    h1[j] = fmaxf(acc, 0.f);
    __syncthreads();
    if (j < NCLS) {
        float o = l2b[j];
#pragma unroll 8
        for (int kk = 0; kk < 64; kk++) o += h1[kk] * l2w[kk * NCLS + j];
        out[b * NCLS + j] = o;
    }
}

// ---------------- host orchestration ----------------------------------------
extern "C" void kernel_launch(void* const* d_in, const int* in_sizes, int n_in,
                              void* d_out, int out_size) {
    const float* x   = (const float*)d_in[0];
    const int* ei    = (const int*)d_in[1];
    const float* W1  = (const float*)d_in[3];
    const float* b1  = (const float*)d_in[4];
    const float* p1  = (const float*)d_in[5];
    const float* W2  = (const float*)d_in[6];
    const float* b2  = (const float*)d_in[7];
    const float* p2  = (const float*)d_in[8];
    const float* l1w = (const float*)d_in[9];
    const float* l1b = (const float*)d_in[10];
    const float* l2w = (const float*)d_in[11];
    const float* l2b = (const float*)d_in[12];
    float* out = (float*)d_out;

    const int4* src4 = (const int4*)ei;
    const int4* dst4 = (const int4*)(ei + EDG);

    float *h, *score, *rdeg, *vals, *x1, *x2;
    __half* xwh;
    int *cnt, *elist, *perm, *newid;
    cudaGetSymbolAddress((void**)&xwh,    g_xw);
    cudaGetSymbolAddress((void**)&h,      g_h);
    cudaGetSymbolAddress((void**)&score,  g_score);
    cudaGetSymbolAddress((void**)&rdeg,   g_rdeg);
    cudaGetSymbolAddress((void**)&cnt,    g_cnt);
    cudaGetSymbolAddress((void**)&elist,  g_elist);
    cudaGetSymbolAddress((void**)&perm,   g_perm);
    cudaGetSymbolAddress((void**)&newid,  g_newid);
    cudaGetSymbolAddress((void**)&vals,   g_vals);
    cudaGetSymbolAddress((void**)&x1,     g_x1);
    cudaGetSymbolAddress((void**)&x2,     g_x2);

    const int TB = 256;
    const int E4 = EDG / 4;
    const int EB4 = (E4 + TB - 1) / TB;

    // ===================== Stage 1 =====================
    init1_kernel<<<256, TB>>>(cnt, newid, NTOT);
    place1_kernel<<<EB4, TB>>>(src4, dst4, cnt, elist, E4);

    matmul64_kernel<<<NTOT / 64, TB>>>(x, W1, nullptr, nullptr, xwh, NTOT, cnt, rdeg);
    conv_kernel<<<(NTOT * 32 + TB - 1) / TB, TB>>>(cnt, elist, rdeg, xwh, b1, p1, h, score, NTOT);

    // topk1: radix-selects, emits perm/vals/newid, zeroes cnt for stage 2, computes x1
    topk_kernel<<<BG, 1024>>>(score, h, NPG, K1, perm, vals, newid, cnt, x1);

    // ===================== Stage 2 =====================
    place2_kernel<<<EB4, TB>>>(src4, dst4, newid, cnt, elist, E4);

    matmul64_kernel<<<NT1 / 64, TB>>>(h, W2, perm, vals, xwh, NT1, cnt, rdeg);
    conv_kernel<<<(NT1 * 32 + TB - 1) / TB, TB>>>(cnt, elist, rdeg, xwh, b2, p2, h, score, NT1);

    // topk2: only the fused readout output (x2) is consumed downstream
    topk_kernel<<<BG, 1024>>>(score, h, K1, K2,
                              (int*)nullptr, (float*)nullptr, (int*)nullptr, (int*)nullptr, x2);

    // ===================== Head =====================
    head_kernel<<<BG, 64>>>(x1, x2, l1w, l1b, l2w, l2b, out);
}

// round 16
// speedup vs baseline: 1.2520x; 1.0103x over previous
#include <cuda_runtime.h>
#include <cuda_fp16.h>
#include <math.h>

#define BG   64
#define NPG  2048
#define EPG  32768
#define NTOT (BG * NPG)         // 131072
#define EDG  (BG * EPG)         // 2097152
#define K1   1639
#define NT1  (BG * K1)          // 104896 (divisible by 64)
#define K2   1312
#define NT2  (BG * K2)          // 83968
#define DIM  64
#define NCLS 6
#define CAP  64                 // fixed CSR bucket capacity (P(deg>=64) ~ 1e-20)
#define FULLMASK 0xFFFFFFFFu

typedef unsigned long long ull;

// ---------------- scratch ----------------------------------------------------
__device__ __half g_xw[NTOT * DIM];      // (A@W) rows fp16; scaled by rdeg in scale_kernel
__device__ float  g_h[NTOT * DIM];       // conv output (relu'd), fp32
__device__ float  g_score[NTOT];
__device__ float  g_rdeg[NTOT];          // rsqrt(deg incl self-loop)
__device__ int    g_cnt[NTOT];           // in-degree (excl self-loop)
__device__ int    g_elist[NTOT * CAP];   // fixed-stride CSR: src per dst-slot
__device__ int    g_perm[NT1];
__device__ float  g_vals[NT1];
__device__ int    g_newid[NTOT];
__device__ float  g_x1[BG * 2 * DIM];
__device__ float  g_x2[BG * 2 * DIM];

// ---------------- packed f32x2 add (PTX-only; ptxas never auto-emits) --------
__device__ __forceinline__ void add2(ull& d, ull a) {
    asm("add.rn.f32x2 %0, %0, %1;" : "+l"(d) : "l"(a));
}

// pack two floats to half2 bits (helper for scale_kernel)
__device__ __forceinline__ unsigned f2_to_h2bits(float2 f) {
    __half2 h = __floats2half2_rn(f.x, f.y);
    return *(unsigned*)&h;
}

// ---------------- stage-1 init: cnt=0, newid=-1 ------------------------------
__global__ void init1_kernel(int* __restrict__ cnt, int* __restrict__ newid, int n) {
    int t = blockIdx.x * blockDim.x + threadIdx.x;
    int stride = gridDim.x * blockDim.x;
    for (; t < n; t += stride) { cnt[t] = 0; newid[t] = -1; }
}

// fused count + place, 4 edges/thread via int4 (stage 1: all edges valid)
__global__ void place1_kernel(const int4* __restrict__ src4, const int4* __restrict__ dst4,
                              int* __restrict__ cnt, int* __restrict__ elist, int nedge4) {
    int t = blockIdx.x * blockDim.x + threadIdx.x;
    if (t >= nedge4) return;
    int4 s = src4[t];
    int4 d = dst4[t];
    int slot;
    slot = atomicAdd(&cnt[d.x], 1); elist[d.x * CAP + slot] = s.x;
    slot = atomicAdd(&cnt[d.y], 1); elist[d.y * CAP + slot] = s.y;
    slot = atomicAdd(&cnt[d.z], 1); elist[d.z * CAP + slot] = s.z;
    slot = atomicAdd(&cnt[d.w], 1); elist[d.w * CAP + slot] = s.w;
}

// fused remap + count + place, 4 edges/thread (stage 2)
__global__ void place2_kernel(const int4* __restrict__ src4, const int4* __restrict__ dst4,
                              const int* __restrict__ newid,
                              int* __restrict__ cnt, int* __restrict__ elist, int nedge4) {
    int t = blockIdx.x * blockDim.x + threadIdx.x;
    if (t >= nedge4) return;
    int4 s = src4[t];
    int4 d = dst4[t];
    int s2, d2, slot;
    s2 = newid[s.x]; d2 = newid[d.x];
    if (s2 >= 0 && d2 >= 0) { slot = atomicAdd(&cnt[d2], 1); elist[d2 * CAP + slot] = s2; }
    s2 = newid[s.y]; d2 = newid[d.y];
    if (s2 >= 0 && d2 >= 0) { slot = atomicAdd(&cnt[d2], 1); elist[d2 * CAP + slot] = s2; }
    s2 = newid[s.z]; d2 = newid[d.z];
    if (s2 >= 0 && d2 >= 0) { slot = atomicAdd(&cnt[d2], 1); elist[d2 * CAP + slot] = s2; }
    s2 = newid[s.w]; d2 = newid[d.w];
    if (s2 >= 0 && d2 >= 0) { slot = atomicAdd(&cnt[d2], 1); elist[d2 * CAP + slot] = s2; }
}

// ---------------- GEMM (UNSCALED): xw16[i] = fp16( (gather(A) @ W)[i] ) ------
// 64-row tile; thread = 4 rows x 4 cols. No cnt/rdeg dependency -> can run
// CONCURRENTLY with the CSR-build kernels on another stream.
// If perm != nullptr, row i of A is A[perm[i]] * vals[i] (fused TopK gather+gate).
__global__ __launch_bounds__(256, 4) void matmul64_kernel(
    const float* __restrict__ A, const float* __restrict__ W,
    const int* __restrict__ perm, const float* __restrict__ vals,
    __half* __restrict__ C, int nrows) {
    __shared__ float Ws[16][64][4];   // [k4][col][k-in-group]
    __shared__ float As[64][64];
    int tid = threadIdx.x;
    // repack W: W[k][j] row-major -> Ws[k>>2][j][k&3]
    for (int i = tid; i < 4096; i += 256) {
        int k = i >> 6, j = i & 63;
        Ws[k >> 2][j][k & 3] = W[i];
    }
    int row0 = blockIdx.x * 64;
    {
        float4* s4 = (float4*)&As[0][0];
        for (int i = tid; i < 1024; i += 256) {
            int grow = row0 + (i >> 4);       // grow < nrows (nrows % 64 == 0)
            int arow = perm ? perm[grow] : grow;
            float sc = perm ? vals[grow] : 1.0f;
            float4 v = ((const float4*)(A + (size_t)arow * 64))[i & 15];
            v.x *= sc; v.y *= sc; v.z *= sc; v.w *= sc;
            s4[i] = v;
        }
    }
    __syncthreads();
    int tx = tid & 15;    // col base
    int ty = tid >> 4;    // rows ty*4 .. ty*4+3
    float acc[4][4] = {};
#pragma unroll
    for (int k4 = 0; k4 < 16; k4++) {
        float4 w[4];
#pragma unroll
        for (int c = 0; c < 4; c++)
            w[c] = *(const float4*)&Ws[k4][tx + 16 * c][0];
#pragma unroll
        for (int r = 0; r < 4; r++) {
            float4 a = *(const float4*)&As[ty * 4 + r][k4 * 4];
#pragma unroll
            for (int c = 0; c < 4; c++)
                acc[r][c] += a.x * w[c].x + a.y * w[c].y + a.z * w[c].z + a.w * w[c].w;
        }
    }
#pragma unroll
    for (int r = 0; r < 4; r++) {
        int row = row0 + ty * 4 + r;
#pragma unroll
        for (int c = 0; c < 4; c++)
            C[(size_t)row * 64 + tx + 16 * c] = __float2half_rn(acc[r][c]);
    }
}

// ---------------- scale pass: rdeg[i]=rsqrt(cnt+1); xw16 row *= rdeg ---------
// Joins the two forked streams (needs cnt from place AND xw from matmul).
// Scaling applied in fp32 before re-rounding to fp16.
__global__ void scale_kernel(__half* __restrict__ xwh, const int* __restrict__ cnt,
                             float* __restrict__ rdeg, int n) {
    int t = blockIdx.x * blockDim.x + threadIdx.x;  // n*8 threads, 8 cols each
    int node = t >> 3, q = t & 7;
    if (node >= n) return;
    float rr = rsqrtf((float)(cnt[node] + 1));
    if (q == 0) rdeg[node] = rr;
    uint4* p = (uint4*)(xwh + (size_t)node * 64 + q * 8);
    uint4 v = *p;
    unsigned* vi = (unsigned*)&v;
#pragma unroll
    for (int i = 0; i < 4; i++) {
        float2 f = __half22float2(*(const __half2*)&vi[i]);
        f.x *= rr; f.y *= rr;
        vi[i] = f2_to_h2bits(f);
    }
    *p = v;
}

// ---------------- fused CSR-gather conv + epilogue + score -------------------
// One warp per dst node; half-warps process alternate edges IN PAIRS:
// two fp16 row slices combined with HADD2, converted once, accumulated fp32.
__global__ __launch_bounds__(256) void conv_kernel(
    const int* __restrict__ cnt, const int* __restrict__ elist,
    const float* __restrict__ rdeg, const __half* __restrict__ xwh,
    const float* __restrict__ bias, const float* __restrict__ p,
    float* __restrict__ h, float* __restrict__ score, int n) {
    int warp = (blockIdx.x * blockDim.x + threadIdx.x) >> 5;
    int lane = threadIdx.x & 31;
    if (warp >= n) return;
    int li   = lane & 15;      // lane covers columns [li*4, li*4+4)
    int half = lane >> 4;
    float rd = rdeg[warp];
    int m = cnt[warp];
    const int* el = elist + (size_t)warp * CAP;
    ull a01 = 0, a23 = 0;      // packed f32x2 accumulators (bits 0 == (0.f,0.f))
    int e = half;
#pragma unroll 2
    for (; e + 2 < m; e += 4) {
        int s0 = el[e], s1 = el[e + 2];
        uint2 v0 = *(const uint2*)((const char*)xwh + ((size_t)s0 << 7) + (li << 3));
        uint2 v1 = *(const uint2*)((const char*)xwh + ((size_t)s1 << 7) + (li << 3));
        __half2 pA = __hadd2(*(const __half2*)&v0.x, *(const __half2*)&v1.x);
        __half2 pB = __hadd2(*(const __half2*)&v0.y, *(const __half2*)&v1.y);
        float2 f0 = __half22float2(pA);
        float2 f1 = __half22float2(pB);
        add2(a01, *(const ull*)&f0);
        add2(a23, *(const ull*)&f1);
    }
    if (e < m) {               // at most one tail edge per half
        int s = el[e];
        uint2 hv = *(const uint2*)((const char*)xwh + ((size_t)s << 7) + (li << 3));
        float2 f0 = __half22float2(*(const __half2*)&hv.x);
        float2 f1 = __half22float2(*(const __half2*)&hv.y);
        add2(a01, *(const ull*)&f0);
        add2(a23, *(const ull*)&f1);
    }
    float2 f01 = *(float2*)&a01;
    float2 f23 = *(float2*)&a23;
    float4 acc = make_float4(f01.x, f01.y, f23.x, f23.y);
    // combine halves (both halves end up with full sums)
    acc.x += __shfl_xor_sync(FULLMASK, acc.x, 16);
    acc.y += __shfl_xor_sync(FULLMASK, acc.y, 16);
    acc.z += __shfl_xor_sync(FULLMASK, acc.z, 16);
    acc.w += __shfl_xor_sync(FULLMASK, acc.w, 16);
    // self-loop term + bias + relu: h = relu(rd*(sum + xw'[dst]) + b)
    uint2 sv = *(const uint2*)((const char*)xwh + ((size_t)warp << 7) + (li << 3));
    float2 s0 = __half22float2(*(const __half2*)&sv.x);
    float2 s1 = __half22float2(*(const __half2*)&sv.y);
    float4 b4 = ((const float4*)bias)[li];
    acc.x = fmaxf((acc.x + s0.x) * rd + b4.x, 0.f);
    acc.y = fmaxf((acc.y + s0.y) * rd + b4.y, 0.f);
    acc.z = fmaxf((acc.z + s1.x) * rd + b4.z, 0.f);
    acc.w = fmaxf((acc.w + s1.y) * rd + b4.w, 0.f);
    if (half == 0) ((float4*)h)[(size_t)warp * 16 + li] = acc;
    // pooling score: tanh(h.p/||p||); duplicated warp sums -> 1/sqrt(2) factor.
    float4 p4 = ((const float4*)p)[li];
    float dot = acc.x * p4.x + acc.y * p4.y + acc.z * p4.z + acc.w * p4.w;
    float pp  = p4.x * p4.x + p4.y * p4.y + p4.z * p4.z + p4.w * p4.w;
#pragma unroll
    for (int o = 16; o; o >>= 1) {
        dot += __shfl_down_sync(FULLMASK, dot, o);
        pp  += __shfl_down_sync(FULLMASK, pp, o);
    }
    if (lane == 0) score[warp] = tanhf(dot * rsqrtf(pp) * 0.7071067811865476f);
}

// ---------------- per-graph top-k via EXACT RADIX-SELECT + fused readout -----
__global__ __launch_bounds__(1024) void topk_kernel(
    const float* __restrict__ score, const float* __restrict__ h,
    int n_per, int k,
    int* __restrict__ perm, float* __restrict__ vals, int* __restrict__ newid,
    int* __restrict__ cnt_zero, float* __restrict__ out) {
    __shared__ unsigned keys[2048];
    __shared__ int sel[2048];
    __shared__ int hist[256];
    __shared__ int sbuf[1024];
    __shared__ float smx[1024], ssm[1024];
    __shared__ int s_thr, s_kRem, s_ctr;
    int b = blockIdx.x;
    int tid = threadIdx.x;
    const float* sc = score + (size_t)b * n_per;
    for (int i = tid; i < 2048; i += 1024) {
        unsigned u = 0;
        if (i < n_per) {
            u = __float_as_uint(sc[i]);
            u = (u & 0x80000000u) ? ~u : (u | 0x80000000u);
        }
        keys[i] = u;
    }
    unsigned pfx = 0, pfxMask = 0;
    int kRem = k;
    for (int shift = 24; shift >= 0; shift -= 8) {
        if (tid < 256) hist[tid] = 0;
        __syncthreads();
        for (int i = tid; i < 2048; i += 1024) {
            unsigned u = keys[i];
            if ((u & pfxMask) == pfx) atomicAdd(&hist[(u >> shift) & 255u], 1);
        }
        __syncthreads();
        if (tid < 256) sbuf[tid] = hist[255 - tid];
        __syncthreads();
        for (int off = 1; off < 256; off <<= 1) {
            int t = (tid < 256 && tid >= off) ? sbuf[tid - off] : 0;
            __syncthreads();
            if (tid < 256) sbuf[tid] += t;
            __syncthreads();
        }
        if (tid < 256) {
            int x = 255 - tid;
            int sInc = sbuf[tid];
            int sExc = sInc - hist[x];
            if (sExc < kRem && kRem <= sInc) { s_thr = x; s_kRem = kRem - sExc; }
        }
        __syncthreads();
        pfx |= ((unsigned)s_thr) << shift;
        pfxMask |= 255u << shift;
        kRem = s_kRem;
        __syncthreads();
    }
    unsigned T = pfx;
    int base = k - kRem;
    if (tid == 0) s_ctr = 0;
    __syncthreads();
    for (int i = tid; i < n_per; i += 1024) {
        if (keys[i] > T) { int pos = atomicAdd(&s_ctr, 1); sel[pos] = i; }
    }
    __syncthreads();
    int i0 = 2 * tid, i1 = 2 * tid + 1;
    int e0 = (i0 < n_per) && (keys[i0] == T);
    int e1 = (i1 < n_per) && (keys[i1] == T);
    sbuf[tid] = e0 + e1;
    __syncthreads();
    for (int off = 1; off < 1024; off <<= 1) {
        int t = (tid >= off) ? sbuf[tid - off] : 0;
        __syncthreads();
        sbuf[tid] += t;
        __syncthreads();
    }
    int pre = sbuf[tid] - (e0 + e1);
    if (e0 && pre < kRem)       sel[base + pre]       = i0;
    if (e1 && pre + e0 < kRem)  sel[base + pre + e0]  = i1;
    __syncthreads();
    for (int r = tid; r < k; r += 1024) {
        int idx = sel[r];
        if (perm)     perm[b * k + r] = b * n_per + idx;
        if (vals)     vals[b * k + r] = sc[idx];
        if (newid)    newid[b * n_per + idx] = b * k + r;
        if (cnt_zero) cnt_zero[b * k + r] = 0;
    }
    int j  = tid & 63;
    int rg = tid >> 6;
    float mx = -INFINITY, sum = 0.f;
    for (int r = rg; r < k; r += 16) {
        int idx = sel[r];
        float val = sc[idx];
        float v = h[((size_t)b * n_per + idx) * 64 + j] * val;
        mx = fmaxf(mx, v);
        sum += v;
    }
    smx[tid] = mx;
    ssm[tid] = sum;
    __syncthreads();
    for (int s = 8; s >= 1; s >>= 1) {
        if (rg < s) {
            smx[rg * 64 + j] = fmaxf(smx[rg * 64 + j], smx[(rg + s) * 64 + j]);
            ssm[rg * 64 + j] += ssm[(rg + s) * 64 + j];
        }
        __syncthreads();
    }
    if (rg == 0) {
        out[b * 128 + j]      = smx[j];
        out[b * 128 + 64 + j] = ssm[j] / (float)k;
    }
}

// ---------------- MLP head ---------------------------------------------------
__global__ __launch_bounds__(64) void head_kernel(
    const float* __restrict__ x1, const float* __restrict__ x2,
    const float* __restrict__ l1w, const float* __restrict__ l1b,
    const float* __restrict__ l2w, const float* __restrict__ l2b,
    float* __restrict__ out) {
    int b = blockIdx.x;
    int j = threadIdx.x;
    __shared__ float hv[128];
    __shared__ float h1[64];
    hv[j]      = x1[b * 128 + j]      + x2[b * 128 + j];
    hv[j + 64] = x1[b * 128 + 64 + j] + x2[b * 128 + 64 + j];
    __syncthreads();
    float acc = l1b[j];
#pragma unroll 8
    for (int k = 0; k < 128; k++) acc += hv[k] * l1w[k * 64 + j];
    h1[j] = fmaxf(acc, 0.f);
    __syncthreads();
    if (j < NCLS) {
        float o = l2b[j];
#pragma unroll 8
        for (int kk = 0; kk < 64; kk++) o += h1[kk] * l2w[kk * NCLS + j];
        out[b * NCLS + j] = o;
    }
}

// ---------------- host orchestration (two-stream fork/join) ------------------
extern "C" void kernel_launch(void* const* d_in, const int* in_sizes, int n_in,
                              void* d_out, int out_size) {
    const float* x   = (const float*)d_in[0];
    const int* ei    = (const int*)d_in[1];
    const float* W1  = (const float*)d_in[3];
    const float* b1  = (const float*)d_in[4];
    const float* p1  = (const float*)d_in[5];
    const float* W2  = (const float*)d_in[6];
    const float* b2  = (const float*)d_in[7];
    const float* p2  = (const float*)d_in[8];
    const float* l1w = (const float*)d_in[9];
    const float* l1b = (const float*)d_in[10];
    const float* l2w = (const float*)d_in[11];
    const float* l2b = (const float*)d_in[12];
    float* out = (float*)d_out;

    const int4* src4 = (const int4*)ei;
    const int4* dst4 = (const int4*)(ei + EDG);

    float *h, *score, *rdeg, *vals, *x1, *x2;
    __half* xwh;
    int *cnt, *elist, *perm, *newid;
    cudaGetSymbolAddress((void**)&xwh,    g_xw);
    cudaGetSymbolAddress((void**)&h,      g_h);
    cudaGetSymbolAddress((void**)&score,  g_score);
    cudaGetSymbolAddress((void**)&rdeg,   g_rdeg);
    cudaGetSymbolAddress((void**)&cnt,    g_cnt);
    cudaGetSymbolAddress((void**)&elist,  g_elist);
    cudaGetSymbolAddress((void**)&perm,   g_perm);
    cudaGetSymbolAddress((void**)&newid,  g_newid);
    cudaGetSymbolAddress((void**)&vals,   g_vals);
    cudaGetSymbolAddress((void**)&x1,     g_x1);
    cudaGetSymbolAddress((void**)&x2,     g_x2);

    // one-time stream/event creation (resource setup only; the launched work
    // is identical on every call — first call is the uncaptured correctness run)
    static cudaStream_t sB = nullptr;
    static cudaEvent_t evRoot, evM1, evT1, evM2;
    if (!sB) {
        cudaStreamCreateWithFlags(&sB, cudaStreamNonBlocking);
        cudaEventCreateWithFlags(&evRoot, cudaEventDisableTiming);
        cudaEventCreateWithFlags(&evM1,   cudaEventDisableTiming);
        cudaEventCreateWithFlags(&evT1,   cudaEventDisableTiming);
        cudaEventCreateWithFlags(&evM2,   cudaEventDisableTiming);
    }
    cudaStream_t sA = 0;   // harness's (capture) stream via default-stream launches

    const int TB = 256;
    const int E4 = EDG / 4;
    const int EB4 = (E4 + TB - 1) / TB;

    // ===================== Stage 1 =====================
    // fork: GEMM (x,W only) on sB concurrent with CSR build on sA
    cudaEventRecord(evRoot, sA);
    cudaStreamWaitEvent(sB, evRoot, 0);
    matmul64_kernel<<<NTOT / 64, TB, 0, sB>>>(x, W1, nullptr, nullptr, xwh, NTOT);
    cudaEventRecord(evM1, sB);

    init1_kernel<<<256, TB, 0, sA>>>(cnt, newid, NTOT);
    place1_kernel<<<EB4, TB, 0, sA>>>(src4, dst4, cnt, elist, E4);

    // join: scale needs cnt (sA) + xw (sB)
    cudaStreamWaitEvent(sA, evM1, 0);
    scale_kernel<<<(NTOT * 8 + TB - 1) / TB, TB, 0, sA>>>(xwh, cnt, rdeg, NTOT);
    conv_kernel<<<(NTOT * 32 + TB - 1) / TB, TB, 0, sA>>>(cnt, elist, rdeg, xwh, b1, p1, h, score, NTOT);
    topk_kernel<<<BG, 1024, 0, sA>>>(score, h, NPG, K1, perm, vals, newid, cnt, x1);

    // ===================== Stage 2 =====================
    // fork: GEMM (h, perm, vals) on sB concurrent with place2 on sA
    cudaEventRecord(evT1, sA);
    cudaStreamWaitEvent(sB, evT1, 0);
    matmul64_kernel<<<NT1 / 64, TB, 0, sB>>>(h, W2, perm, vals, xwh, NT1);
    cudaEventRecord(evM2, sB);

    place2_kernel<<<EB4, TB, 0, sA>>>(src4, dst4, newid, cnt, elist, E4);

    cudaStreamWaitEvent(sA, evM2, 0);
    scale_kernel<<<(NT1 * 8 + TB - 1) / TB, TB, 0, sA>>>(xwh, cnt, rdeg, NT1);
    conv_kernel<<<(NT1 * 32 + TB - 1) / TB, TB, 0, sA>>>(cnt, elist, rdeg, xwh, b2, p2, h, score, NT1);
    topk_kernel<<<BG, 1024, 0, sA>>>(score, h, K1, K2,
                                     (int*)nullptr, (float*)nullptr, (int*)nullptr, (int*)nullptr, x2);

    // ===================== Head =====================
    head_kernel<<<BG, 64, 0, sA>>>(x1, x2, l1w, l1b, l2w, l2b, out);
}